// round 1
// baseline (speedup 1.0000x reference)
#include <cuda_runtime.h>
#include <cuda_bf16.h>

#define Bn 8
#define Hn 128
#define Wn 128
#define Cn 512
#define NCOL (Bn*Wn)          /* 1024 (b,w) columns */
#define MTOT (Bn*Hn*Wn)       /* 131072 rows for QKV GEMM */

// Scratch for q,k,v in transposed layout [B, W, H, C] so that each (b,w)
// attention column is a contiguous [128][512] panel.
__device__ float g_q[(size_t)NCOL * Hn * Cn];
__device__ float g_k[(size_t)NCOL * Hn * Cn];
__device__ float g_v[(size_t)NCOL * Hn * Cn];

// ---------------------------------------------------------------------------
// Kernel 1: q/k/v = x @ W^T   (W is [C,C], row-major; x rows are K-major too)
// Tile 128x128x16, 256 threads, 8x8 per thread, fp32.
// blockIdx.z selects which of Wq/Wk/Wv (and destination).
// Epilogue writes TRANSPOSED: m=(b*H+h)*W+w  ->  row (b*W+w)*H+h.
// ---------------------------------------------------------------------------
__global__ __launch_bounds__(256)
void qkv_gemm(const float* __restrict__ x, const float* __restrict__ Wq,
              const float* __restrict__ Wk, const float* __restrict__ Wv)
{
    __shared__ float As[16 * 132];   // [k][m], padded stride 132 (16B-aligned rows)
    __shared__ float Bs[16 * 132];   // [k][n]

    const int which = blockIdx.z;
    const float* Wm = (which == 0) ? Wq : (which == 1) ? Wk : Wv;
    float* dst      = (which == 0) ? g_q : (which == 1) ? g_k : g_v;

    const int m0  = blockIdx.y * 128;
    const int n0  = blockIdx.x * 128;
    const int tid = threadIdx.x;
    const int tm  = (tid >> 4) * 8;
    const int tn  = (tid & 15) * 8;

    float acc[8][8];
#pragma unroll
    for (int i = 0; i < 8; i++)
#pragma unroll
        for (int j = 0; j < 8; j++) acc[i][j] = 0.f;

    const int lr = tid >> 2;          // 0..63
    const int lc = (tid & 3) * 4;     // 0,4,8,12

    for (int k0 = 0; k0 < Cn; k0 += 16) {
#pragma unroll
        for (int t = 0; t < 2; t++) {
            const int r = lr + t * 64;
            float4 av = *(const float4*)(x  + (size_t)(m0 + r) * Cn + k0 + lc);
            As[(lc + 0) * 132 + r] = av.x;
            As[(lc + 1) * 132 + r] = av.y;
            As[(lc + 2) * 132 + r] = av.z;
            As[(lc + 3) * 132 + r] = av.w;
            float4 bv = *(const float4*)(Wm + (size_t)(n0 + r) * Cn + k0 + lc);
            Bs[(lc + 0) * 132 + r] = bv.x;
            Bs[(lc + 1) * 132 + r] = bv.y;
            Bs[(lc + 2) * 132 + r] = bv.z;
            Bs[(lc + 3) * 132 + r] = bv.w;
        }
        __syncthreads();
#pragma unroll
        for (int kk = 0; kk < 16; kk++) {
            float4 a0 = *(const float4*)&As[kk * 132 + tm];
            float4 a1 = *(const float4*)&As[kk * 132 + tm + 4];
            float4 b0 = *(const float4*)&Bs[kk * 132 + tn];
            float4 b1 = *(const float4*)&Bs[kk * 132 + tn + 4];
            float a[8] = {a0.x, a0.y, a0.z, a0.w, a1.x, a1.y, a1.z, a1.w};
            float b[8] = {b0.x, b0.y, b0.z, b0.w, b1.x, b1.y, b1.z, b1.w};
#pragma unroll
            for (int i = 0; i < 8; i++)
#pragma unroll
                for (int j = 0; j < 8; j++)
                    acc[i][j] = fmaf(a[i], b[j], acc[i][j]);
        }
        __syncthreads();
    }

    // Within one 128-row m-tile, (b,h) are fixed and w = row-in-tile
    const int b = m0 >> 14;           // / (H*W)
    const int h = (m0 >> 7) & 127;
#pragma unroll
    for (int i = 0; i < 8; i++) {
        const int w = tm + i;
        const size_t off = ((size_t)((b * Wn + w) * Hn + h)) * Cn + n0 + tn;
        *(float4*)(dst + off)     = make_float4(acc[i][0], acc[i][1], acc[i][2], acc[i][3]);
        *(float4*)(dst + off + 4) = make_float4(acc[i][4], acc[i][5], acc[i][6], acc[i][7]);
    }
}

// ---------------------------------------------------------------------------
// Kernel 2: per-(b,w)-column criss-cross attention along H.
//   E = Q K^T (128x128, K-dim 512), diag = -inf, row softmax,
//   out = gamma * (A @ V) + x, written in original [B,H,W,C] layout.
// One CTA per column, 256 threads, 96KB dynamic smem.
// ---------------------------------------------------------------------------
__global__ __launch_bounds__(256)
void cc_attn(const float* __restrict__ x, const float* __restrict__ gamma_p,
             float* __restrict__ out)
{
    extern __shared__ float sm[];
    float* E  = sm;                 // 128*128 = 16384 floats (64KB), persists
    float* Qs = sm + 16384;         // phase-1 tile, 16*132
    float* Ks = Qs + 16 * 132;      // phase-1 tile, 16*132
    float* Vs = sm + 16384;         // phase-2 reuse of Qs/Ks region, 128*64

    const int bw  = blockIdx.x;     // b*128 + w
    const int b   = bw >> 7;
    const int w   = bw & 127;
    const int tid = threadIdx.x;
    const int tm  = (tid >> 4) * 8;
    const int tn  = (tid & 15) * 8;

    const float* qcol = g_q + (size_t)bw * (Hn * Cn);
    const float* kcol = g_k + (size_t)bw * (Hn * Cn);
    const float* vcol = g_v + (size_t)bw * (Hn * Cn);

    // ---- Phase 1: energy = Q @ K^T ----
    float acc[8][8];
#pragma unroll
    for (int i = 0; i < 8; i++)
#pragma unroll
        for (int j = 0; j < 8; j++) acc[i][j] = 0.f;

    const int lr = tid >> 2;
    const int lc = (tid & 3) * 4;

    for (int k0 = 0; k0 < Cn; k0 += 16) {
#pragma unroll
        for (int t = 0; t < 2; t++) {
            const int r = lr + t * 64;
            float4 qv = *(const float4*)(qcol + (size_t)r * Cn + k0 + lc);
            Qs[(lc + 0) * 132 + r] = qv.x;
            Qs[(lc + 1) * 132 + r] = qv.y;
            Qs[(lc + 2) * 132 + r] = qv.z;
            Qs[(lc + 3) * 132 + r] = qv.w;
            float4 kv = *(const float4*)(kcol + (size_t)r * Cn + k0 + lc);
            Ks[(lc + 0) * 132 + r] = kv.x;
            Ks[(lc + 1) * 132 + r] = kv.y;
            Ks[(lc + 2) * 132 + r] = kv.z;
            Ks[(lc + 3) * 132 + r] = kv.w;
        }
        __syncthreads();
#pragma unroll
        for (int kk = 0; kk < 16; kk++) {
            float4 a0 = *(const float4*)&Qs[kk * 132 + tm];
            float4 a1 = *(const float4*)&Qs[kk * 132 + tm + 4];
            float4 b0 = *(const float4*)&Ks[kk * 132 + tn];
            float4 b1 = *(const float4*)&Ks[kk * 132 + tn + 4];
            float a[8] = {a0.x, a0.y, a0.z, a0.w, a1.x, a1.y, a1.z, a1.w};
            float bb[8] = {b0.x, b0.y, b0.z, b0.w, b1.x, b1.y, b1.z, b1.w};
#pragma unroll
            for (int i = 0; i < 8; i++)
#pragma unroll
                for (int j = 0; j < 8; j++)
                    acc[i][j] = fmaf(a[i], bb[j], acc[i][j]);
        }
        __syncthreads();
    }

    // write E with the diagonal masked to -inf
    const float NEG_INF = __int_as_float(0xff800000);
#pragma unroll
    for (int i = 0; i < 8; i++) {
        const int h = tm + i;
#pragma unroll
        for (int j = 0; j < 8; j++) {
            const int g = tn + j;
            E[h * 128 + g] = (h == g) ? NEG_INF : acc[i][j];
        }
    }
    __syncthreads();

    // ---- softmax over g, one warp per row (8 warps x 16 rows) ----
    const int warp = tid >> 5, lane = tid & 31;
    for (int r = warp; r < 128; r += 8) {
        float* row = E + r * 128;
        float v0 = row[lane], v1 = row[lane + 32], v2 = row[lane + 64], v3 = row[lane + 96];
        float mx = fmaxf(fmaxf(v0, v1), fmaxf(v2, v3));
#pragma unroll
        for (int o = 16; o > 0; o >>= 1) mx = fmaxf(mx, __shfl_xor_sync(0xffffffffu, mx, o));
        v0 = __expf(v0 - mx); v1 = __expf(v1 - mx);
        v2 = __expf(v2 - mx); v3 = __expf(v3 - mx);
        float s = v0 + v1 + v2 + v3;
#pragma unroll
        for (int o = 16; o > 0; o >>= 1) s += __shfl_xor_sync(0xffffffffu, s, o);
        const float inv = 1.f / s;
        row[lane] = v0 * inv; row[lane + 32] = v1 * inv;
        row[lane + 64] = v2 * inv; row[lane + 96] = v3 * inv;
    }
    __syncthreads();

    // ---- Phase 2: out = gamma * (A @ V) + x ----
    const float gam = gamma_p[0];
    const int tn2 = (tid & 15) * 4;
    for (int n0 = 0; n0 < Cn; n0 += 64) {
        __syncthreads();   // previous chunk's Vs reads complete before overwrite
#pragma unroll
        for (int t = 0; t < 8; t++) {
            const int idx = tid + t * 256;      // float4 index, 0..2047
            const int g = idx >> 4;
            const int c = (idx & 15) * 4;
            *(float4*)&Vs[g * 64 + c] = *(const float4*)(vcol + (size_t)g * Cn + n0 + c);
        }
        __syncthreads();

        float a2[8][4];
#pragma unroll
        for (int i = 0; i < 8; i++)
#pragma unroll
            for (int j = 0; j < 4; j++) a2[i][j] = 0.f;

#pragma unroll 2
        for (int g = 0; g < 128; g++) {
            const float4 bv = *(const float4*)&Vs[g * 64 + tn2];
#pragma unroll
            for (int i = 0; i < 8; i++) {
                const float a = E[(tm + i) * 128 + g];   // 2 distinct addrs/warp -> broadcast
                a2[i][0] = fmaf(a, bv.x, a2[i][0]);
                a2[i][1] = fmaf(a, bv.y, a2[i][1]);
                a2[i][2] = fmaf(a, bv.z, a2[i][2]);
                a2[i][3] = fmaf(a, bv.w, a2[i][3]);
            }
        }

#pragma unroll
        for (int i = 0; i < 8; i++) {
            const int h = tm + i;
            const size_t off = ((size_t)(b * Hn + h) * Wn + w) * Cn + n0 + tn2;
            const float4 xv = *(const float4*)(x + off);
            float4 rv;
            rv.x = fmaf(gam, a2[i][0], xv.x);
            rv.y = fmaf(gam, a2[i][1], xv.y);
            rv.z = fmaf(gam, a2[i][2], xv.z);
            rv.w = fmaf(gam, a2[i][3], xv.w);
            *(float4*)(out + off) = rv;
        }
    }
}

// ---------------------------------------------------------------------------
extern "C" void kernel_launch(void* const* d_in, const int* in_sizes, int n_in,
                              void* d_out, int out_size)
{
    const float* x  = (const float*)d_in[0];
    const float* Wq = (const float*)d_in[1];
    const float* Wk = (const float*)d_in[2];
    const float* Wv = (const float*)d_in[3];
    const float* gm = (const float*)d_in[4];
    float* out = (float*)d_out;

    // QKV projections into transposed scratch
    dim3 grid_g(Cn / 128, MTOT / 128, 3);   // (4, 1024, 3)
    qkv_gemm<<<grid_g, 256>>>(x, Wq, Wk, Wv);

    // Attention: one CTA per (b,w) column, 96KB dynamic smem
    cudaFuncSetAttribute(cc_attn, cudaFuncAttributeMaxDynamicSharedMemorySize, 98304);
    cc_attn<<<NCOL, 256, 98304>>>(x, gm, out);
}

// round 4
// speedup vs baseline: 1.7688x; 1.7688x over previous
#include <cuda_runtime.h>
#include <cuda_bf16.h>
#include <cstdint>

#define Bn 8
#define Hn 128
#define Wn 128
#define Cn 512
#define NCOL (Bn*Wn)          /* 1024 (b,w) columns */
#define MTOT (Bn*Hn*Wn)       /* 131072 rows for QKV GEMM */
#define NTOT (3*Cn)           /* 1536 combined output cols (q|k|v) */

// fp32 q,k,v in transposed layout [B, W, H, C]
__device__ float g_q[(size_t)NCOL * Hn * Cn];
__device__ float g_k[(size_t)NCOL * Hn * Cn];
__device__ float g_v[(size_t)NCOL * Hn * Cn];
// bf16 hi/lo splits of x and concatenated weights [Wq;Wk;Wv]
__device__ __nv_bfloat16 g_xhi[(size_t)MTOT * Cn];
__device__ __nv_bfloat16 g_xlo[(size_t)MTOT * Cn];
__device__ __nv_bfloat16 g_whi[(size_t)NTOT * Cn];
__device__ __nv_bfloat16 g_wlo[(size_t)NTOT * Cn];

__device__ __forceinline__ uint32_t smem_u32(const void* p) {
    uint32_t a;
    asm("{ .reg .u64 t; cvta.to.shared.u64 t, %1; cvt.u32.u64 %0, t; }" : "=r"(a) : "l"(p));
    return a;
}
__device__ __forceinline__ void ldsm_x4(uint32_t* r, uint32_t addr) {
    asm volatile("ldmatrix.sync.aligned.m8n8.x4.shared.b16 {%0,%1,%2,%3}, [%4];"
                 : "=r"(r[0]), "=r"(r[1]), "=r"(r[2]), "=r"(r[3]) : "r"(addr));
}
__device__ __forceinline__ void ldsm_x2(uint32_t* r, uint32_t addr) {
    asm volatile("ldmatrix.sync.aligned.m8n8.x2.shared.b16 {%0,%1}, [%2];"
                 : "=r"(r[0]), "=r"(r[1]) : "r"(addr));
}
__device__ __forceinline__ void mma_bf16(float* c, const uint32_t* a, const uint32_t* b) {
    asm volatile("mma.sync.aligned.m16n8k16.row.col.f32.bf16.bf16.f32 "
                 "{%0,%1,%2,%3}, {%4,%5,%6,%7}, {%8,%9}, {%0,%1,%2,%3};"
                 : "+f"(c[0]), "+f"(c[1]), "+f"(c[2]), "+f"(c[3])
                 : "r"(a[0]), "r"(a[1]), "r"(a[2]), "r"(a[3]), "r"(b[0]), "r"(b[1]));
}
__device__ __forceinline__ void cp16(uint32_t dst, const void* src) {
    asm volatile("cp.async.cg.shared.global [%0], [%1], 16;"
                 :: "r"(dst), "l"(__cvta_generic_to_global(src)) : "memory");
}

// ---------------------------------------------------------------------------
// Prep: split fp32 -> bf16 hi + lo
// ---------------------------------------------------------------------------
__global__ __launch_bounds__(256)
void split_x(const float4* __restrict__ x)
{
    size_t i = (size_t)blockIdx.x * 256 + threadIdx.x;
    float4 v = x[i];
    __nv_bfloat16 h0 = __float2bfloat16(v.x), h1 = __float2bfloat16(v.y);
    __nv_bfloat16 h2 = __float2bfloat16(v.z), h3 = __float2bfloat16(v.w);
    __nv_bfloat16 l0 = __float2bfloat16(v.x - __bfloat162float(h0));
    __nv_bfloat16 l1 = __float2bfloat16(v.y - __bfloat162float(h1));
    __nv_bfloat16 l2 = __float2bfloat16(v.z - __bfloat162float(h2));
    __nv_bfloat16 l3 = __float2bfloat16(v.w - __bfloat162float(h3));
    uint2 uh, ul;
    uh.x = (uint32_t)__bfloat16_as_ushort(h0) | ((uint32_t)__bfloat16_as_ushort(h1) << 16);
    uh.y = (uint32_t)__bfloat16_as_ushort(h2) | ((uint32_t)__bfloat16_as_ushort(h3) << 16);
    ul.x = (uint32_t)__bfloat16_as_ushort(l0) | ((uint32_t)__bfloat16_as_ushort(l1) << 16);
    ul.y = (uint32_t)__bfloat16_as_ushort(l2) | ((uint32_t)__bfloat16_as_ushort(l3) << 16);
    ((uint2*)g_xhi)[i] = uh;
    ((uint2*)g_xlo)[i] = ul;
}

__global__ __launch_bounds__(256)
void split_w(const float* __restrict__ Wq, const float* __restrict__ Wk,
             const float* __restrict__ Wv)
{
    size_t i = (size_t)blockIdx.x * 256 + threadIdx.x;
    size_t e = i * 4;
    int r = (int)(e >> 9);
    int c = (int)(e & 511);
    const float* W = (r < 512) ? Wq : (r < 1024) ? Wk : Wv;
    float4 v = *(const float4*)(W + (size_t)(r & 511) * Cn + c);
    __nv_bfloat16 h0 = __float2bfloat16(v.x), h1 = __float2bfloat16(v.y);
    __nv_bfloat16 h2 = __float2bfloat16(v.z), h3 = __float2bfloat16(v.w);
    __nv_bfloat16 l0 = __float2bfloat16(v.x - __bfloat162float(h0));
    __nv_bfloat16 l1 = __float2bfloat16(v.y - __bfloat162float(h1));
    __nv_bfloat16 l2 = __float2bfloat16(v.z - __bfloat162float(h2));
    __nv_bfloat16 l3 = __float2bfloat16(v.w - __bfloat162float(h3));
    uint2 uh, ul;
    uh.x = (uint32_t)__bfloat16_as_ushort(h0) | ((uint32_t)__bfloat16_as_ushort(h1) << 16);
    uh.y = (uint32_t)__bfloat16_as_ushort(h2) | ((uint32_t)__bfloat16_as_ushort(h3) << 16);
    ul.x = (uint32_t)__bfloat16_as_ushort(l0) | ((uint32_t)__bfloat16_as_ushort(l1) << 16);
    ul.y = (uint32_t)__bfloat16_as_ushort(l2) | ((uint32_t)__bfloat16_as_ushort(l3) << 16);
    ((uint2*)g_whi)[i] = uh;
    ((uint2*)g_wlo)[i] = ul;
}

// ---------------------------------------------------------------------------
// mma.sync GEMM: D = Xsplit @ Wsplit^T, 3-term hi/lo split (hh + hl + lh).
// CTA 128x128, K-chunk 32, 8 warps (2x4), warp tile 64x32.
// Smem tile: [128 rows][40 bf16] padded (80B row stride, conflict-free ldmatrix).
// ---------------------------------------------------------------------------
#define KCH 32
#define NCHUNK (Cn / KCH)         /* 16 */
#define TILE_B 10240              /* 128*40*2 bytes */
#define STG_B  (4 * TILE_B)       /* Ahi Alo Bhi Blo */

__global__ __launch_bounds__(256, 1)
void qkv_mma()
{
    extern __shared__ char sm[];
    const uint32_t sb = smem_u32(sm);
    const int tid  = threadIdx.x;
    const int wid  = tid >> 5, lane = tid & 31;
    const int m0   = blockIdx.y * 128;
    const int n0g  = blockIdx.x * 128;

    const int warp_m = (wid >> 2) * 64;     // 0 or 64
    const int warp_n = (wid & 3) * 32;      // 0,32,64,96

    const __nv_bfloat16* xa_hi = g_xhi + (size_t)m0 * Cn;
    const __nv_bfloat16* xa_lo = g_xlo + (size_t)m0 * Cn;
    const __nv_bfloat16* wb_hi = g_whi + (size_t)n0g * Cn;
    const __nv_bfloat16* wb_lo = g_wlo + (size_t)n0g * Cn;

    auto load_chunk = [&](int s, int k0) {
        const uint32_t stg = sb + s * STG_B;
#pragma unroll
        for (int t = 0; t < 2; t++) {
            const int idx = tid + t * 256;          // 0..511
            const int row = idx >> 2, seg = idx & 3;
            const uint32_t doff = (uint32_t)(row * 80 + seg * 16);
            const size_t goff = (size_t)row * Cn + k0 + seg * 8;
            cp16(stg + doff,              xa_hi + goff);
            cp16(stg + 2*TILE_B + doff,   wb_hi + goff);
            cp16(stg + TILE_B + doff,     xa_lo + goff);
            cp16(stg + 3*TILE_B + doff,   wb_lo + goff);
        }
        asm volatile("cp.async.commit_group;" ::: "memory");
    };

    float acc[4][4][4];
#pragma unroll
    for (int i = 0; i < 4; i++)
#pragma unroll
        for (int j = 0; j < 4; j++)
#pragma unroll
            for (int q = 0; q < 4; q++) acc[i][j][q] = 0.f;

    const uint32_t a_lane = (uint32_t)((lane & 15) * 80 + (lane >> 4) * 16);
    const uint32_t b_lane = (uint32_t)((lane & 7) * 80 + ((lane >> 3) & 1) * 16);

    load_chunk(0, 0);
    load_chunk(1, KCH);

    for (int k = 0; k < NCHUNK; k++) {
        const int s = k & 1;
        const uint32_t stg = sb + s * STG_B;

        if (k + 2 < NCHUNK) asm volatile("cp.async.wait_group 1;" ::: "memory");
        else                asm volatile("cp.async.wait_group 0;" ::: "memory");
        __syncthreads();

        const uint32_t a_hi_base = stg            + warp_m * 80 + a_lane;
        const uint32_t a_lo_base = stg + TILE_B   + warp_m * 80 + a_lane;
        const uint32_t b_hi_base = stg + 2*TILE_B + warp_n * 80 + b_lane;
        const uint32_t b_lo_base = stg + 3*TILE_B + warp_n * 80 + b_lane;

#pragma unroll
        for (int ks = 0; ks < 2; ks++) {
            uint32_t ah[4][4], bh[4][2];
#pragma unroll
            for (int mf = 0; mf < 4; mf++)
                ldsm_x4(ah[mf], a_hi_base + mf * (16 * 80) + ks * 32);
#pragma unroll
            for (int nf = 0; nf < 4; nf++)
                ldsm_x2(bh[nf], b_hi_base + nf * (8 * 80) + ks * 32);
#pragma unroll
            for (int mf = 0; mf < 4; mf++)
#pragma unroll
                for (int nf = 0; nf < 4; nf++)
                    mma_bf16(acc[mf][nf], ah[mf], bh[nf]);

            uint32_t bl[4][2];
#pragma unroll
            for (int nf = 0; nf < 4; nf++)
                ldsm_x2(bl[nf], b_lo_base + nf * (8 * 80) + ks * 32);
#pragma unroll
            for (int mf = 0; mf < 4; mf++)
#pragma unroll
                for (int nf = 0; nf < 4; nf++)
                    mma_bf16(acc[mf][nf], ah[mf], bl[nf]);

            uint32_t al[4][4];
#pragma unroll
            for (int mf = 0; mf < 4; mf++)
                ldsm_x4(al[mf], a_lo_base + mf * (16 * 80) + ks * 32);
#pragma unroll
            for (int mf = 0; mf < 4; mf++)
#pragma unroll
                for (int nf = 0; nf < 4; nf++)
                    mma_bf16(acc[mf][nf], al[mf], bh[nf]);
        }
        __syncthreads();

        if (k + 2 < NCHUNK) load_chunk(s, (k + 2) * KCH);
    }

    // epilogue: scatter to g_q/g_k/g_v in [B,W,H,C] layout
    const int b  = m0 >> 14;
    const int h  = (m0 >> 7) & 127;
    const int which = n0g >> 9;
    const int col0  = (n0g & 511) + warp_n;
    float* dst = (which == 0) ? g_q : (which == 1) ? g_k : g_v;

    const int g   = lane >> 2;
    const int c2i = (lane & 3) * 2;
#pragma unroll
    for (int mf = 0; mf < 4; mf++) {
        const int w0 = warp_m + mf * 16 + g;
        const size_t r0 = ((size_t)(b * Wn + w0)     * Hn + h) * Cn + col0 + c2i;
        const size_t r1 = ((size_t)(b * Wn + w0 + 8) * Hn + h) * Cn + col0 + c2i;
#pragma unroll
        for (int nf = 0; nf < 4; nf++) {
            *(float2*)(dst + r0 + nf * 8) = make_float2(acc[mf][nf][0], acc[mf][nf][1]);
            *(float2*)(dst + r1 + nf * 8) = make_float2(acc[mf][nf][2], acc[mf][nf][3]);
        }
    }
}

// ---------------------------------------------------------------------------
// Kernel 2: per-(b,w)-column criss-cross attention along H (fp32).
// ---------------------------------------------------------------------------
__global__ __launch_bounds__(256)
void cc_attn(const float* __restrict__ x, const float* __restrict__ gamma_p,
             float* __restrict__ out)
{
    extern __shared__ float smf[];
    float* E  = smf;
    float* Qs = smf + 16384;
    float* Ks = Qs + 16 * 132;
    float* Vs = smf + 16384;

    const int bw  = blockIdx.x;
    const int b   = bw >> 7;
    const int w   = bw & 127;
    const int tid = threadIdx.x;
    const int tm  = (tid >> 4) * 8;
    const int tn  = (tid & 15) * 8;

    const float* qcol = g_q + (size_t)bw * (Hn * Cn);
    const float* kcol = g_k + (size_t)bw * (Hn * Cn);
    const float* vcol = g_v + (size_t)bw * (Hn * Cn);

    float acc[8][8];
#pragma unroll
    for (int i = 0; i < 8; i++)
#pragma unroll
        for (int j = 0; j < 8; j++) acc[i][j] = 0.f;

    const int lr = tid >> 2;
    const int lc = (tid & 3) * 4;

    for (int k0 = 0; k0 < Cn; k0 += 16) {
#pragma unroll
        for (int t = 0; t < 2; t++) {
            const int r = lr + t * 64;
            float4 qv = *(const float4*)(qcol + (size_t)r * Cn + k0 + lc);
            Qs[(lc + 0) * 132 + r] = qv.x;
            Qs[(lc + 1) * 132 + r] = qv.y;
            Qs[(lc + 2) * 132 + r] = qv.z;
            Qs[(lc + 3) * 132 + r] = qv.w;
            float4 kv = *(const float4*)(kcol + (size_t)r * Cn + k0 + lc);
            Ks[(lc + 0) * 132 + r] = kv.x;
            Ks[(lc + 1) * 132 + r] = kv.y;
            Ks[(lc + 2) * 132 + r] = kv.z;
            Ks[(lc + 3) * 132 + r] = kv.w;
        }
        __syncthreads();
#pragma unroll
        for (int kk = 0; kk < 16; kk++) {
            float4 a0 = *(const float4*)&Qs[kk * 132 + tm];
            float4 a1 = *(const float4*)&Qs[kk * 132 + tm + 4];
            float4 b0 = *(const float4*)&Ks[kk * 132 + tn];
            float4 b1 = *(const float4*)&Ks[kk * 132 + tn + 4];
            float a[8] = {a0.x, a0.y, a0.z, a0.w, a1.x, a1.y, a1.z, a1.w};
            float bb[8] = {b0.x, b0.y, b0.z, b0.w, b1.x, b1.y, b1.z, b1.w};
#pragma unroll
            for (int i = 0; i < 8; i++)
#pragma unroll
                for (int j = 0; j < 8; j++)
                    acc[i][j] = fmaf(a[i], bb[j], acc[i][j]);
        }
        __syncthreads();
    }

    const float NEG_INF = __int_as_float(0xff800000);
#pragma unroll
    for (int i = 0; i < 8; i++) {
        const int h = tm + i;
#pragma unroll
        for (int j = 0; j < 8; j++) {
            const int g = tn + j;
            E[h * 128 + g] = (h == g) ? NEG_INF : acc[i][j];
        }
    }
    __syncthreads();

    const int warp = tid >> 5, lane = tid & 31;
    for (int r = warp; r < 128; r += 8) {
        float* row = E + r * 128;
        float v0 = row[lane], v1 = row[lane + 32], v2 = row[lane + 64], v3 = row[lane + 96];
        float mx = fmaxf(fmaxf(v0, v1), fmaxf(v2, v3));
#pragma unroll
        for (int o = 16; o > 0; o >>= 1) mx = fmaxf(mx, __shfl_xor_sync(0xffffffffu, mx, o));
        v0 = __expf(v0 - mx); v1 = __expf(v1 - mx);
        v2 = __expf(v2 - mx); v3 = __expf(v3 - mx);
        float s = v0 + v1 + v2 + v3;
#pragma unroll
        for (int o = 16; o > 0; o >>= 1) s += __shfl_xor_sync(0xffffffffu, s, o);
        const float inv = 1.f / s;
        row[lane] = v0 * inv; row[lane + 32] = v1 * inv;
        row[lane + 64] = v2 * inv; row[lane + 96] = v3 * inv;
    }
    __syncthreads();

    const float gam = gamma_p[0];
    const int tn2 = (tid & 15) * 4;
    for (int n0 = 0; n0 < Cn; n0 += 64) {
        __syncthreads();
#pragma unroll
        for (int t = 0; t < 8; t++) {
            const int idx = tid + t * 256;
            const int g = idx >> 4;
            const int c = (idx & 15) * 4;
            *(float4*)&Vs[g * 64 + c] = *(const float4*)(vcol + (size_t)g * Cn + n0 + c);
        }
        __syncthreads();

        float a2[8][4];
#pragma unroll
        for (int i = 0; i < 8; i++)
#pragma unroll
            for (int j = 0; j < 4; j++) a2[i][j] = 0.f;

#pragma unroll 2
        for (int g = 0; g < 128; g++) {
            const float4 bv = *(const float4*)&Vs[g * 64 + tn2];
#pragma unroll
            for (int i = 0; i < 8; i++) {
                const float a = E[(tm + i) * 128 + g];
                a2[i][0] = fmaf(a, bv.x, a2[i][0]);
                a2[i][1] = fmaf(a, bv.y, a2[i][1]);
                a2[i][2] = fmaf(a, bv.z, a2[i][2]);
                a2[i][3] = fmaf(a, bv.w, a2[i][3]);
            }
        }

#pragma unroll
        for (int i = 0; i < 8; i++) {
            const int h = tm + i;
            const size_t off = ((size_t)(b * Hn + h) * Wn + w) * Cn + n0 + tn2;
            const float4 xv = *(const float4*)(x + off);
            float4 rv;
            rv.x = fmaf(gam, a2[i][0], xv.x);
            rv.y = fmaf(gam, a2[i][1], xv.y);
            rv.z = fmaf(gam, a2[i][2], xv.z);
            rv.w = fmaf(gam, a2[i][3], xv.w);
            *(float4*)(out + off) = rv;
        }
    }
}

// ---------------------------------------------------------------------------
extern "C" void kernel_launch(void* const* d_in, const int* in_sizes, int n_in,
                              void* d_out, int out_size)
{
    const float* x  = (const float*)d_in[0];
    const float* Wq = (const float*)d_in[1];
    const float* Wk = (const float*)d_in[2];
    const float* Wv = (const float*)d_in[3];
    const float* gm = (const float*)d_in[4];
    float* out = (float*)d_out;

    split_x<<<(size_t)MTOT * Cn / 4 / 256, 256>>>((const float4*)x);
    split_w<<<(size_t)NTOT * Cn / 4 / 256, 256>>>(Wq, Wk, Wv);

    const int gemm_smem = 2 * STG_B;   // 81920
    cudaFuncSetAttribute(qkv_mma, cudaFuncAttributeMaxDynamicSharedMemorySize, gemm_smem);
    dim3 grid_g(NTOT / 128, MTOT / 128);   // (12, 1024), all 3-term
    qkv_mma<<<grid_g, 256, gemm_smem>>>();

    cudaFuncSetAttribute(cc_attn, cudaFuncAttributeMaxDynamicSharedMemorySize, 98304);
    cc_attn<<<NCOL, 256, 98304>>>(x, gm, out);
}

// round 5
// speedup vs baseline: 1.9185x; 1.0846x over previous
#include <cuda_runtime.h>
#include <cuda_bf16.h>
#include <cstdint>

#define Bn 8
#define Hn 128
#define Wn 128
#define Cn 512
#define NCOL (Bn*Wn)          /* 1024 (b,w) columns */
#define MTOT (Bn*Hn*Wn)       /* 131072 rows for QKV GEMM */
#define NTOT (3*Cn)           /* 1536 combined output cols (q|k|v) */

// bf16 hi/lo splits of x and concatenated weights [Wq;Wk;Wv]
__device__ __nv_bfloat16 g_xhi[(size_t)MTOT * Cn];
__device__ __nv_bfloat16 g_xlo[(size_t)MTOT * Cn];
__device__ __nv_bfloat16 g_whi[(size_t)NTOT * Cn];
__device__ __nv_bfloat16 g_wlo[(size_t)NTOT * Cn];
// q,k,v in transposed layout [B, W, H, C], bf16 hi/lo pairs
__device__ __nv_bfloat16 g_qh[(size_t)NCOL * Hn * Cn];
__device__ __nv_bfloat16 g_ql[(size_t)NCOL * Hn * Cn];
__device__ __nv_bfloat16 g_kh[(size_t)NCOL * Hn * Cn];
__device__ __nv_bfloat16 g_kl[(size_t)NCOL * Hn * Cn];
__device__ __nv_bfloat16 g_vh[(size_t)NCOL * Hn * Cn];
__device__ __nv_bfloat16 g_vl[(size_t)NCOL * Hn * Cn];

__device__ __forceinline__ uint32_t smem_u32(const void* p) {
    uint32_t a;
    asm("{ .reg .u64 t; cvta.to.shared.u64 t, %1; cvt.u32.u64 %0, t; }" : "=r"(a) : "l"(p));
    return a;
}
__device__ __forceinline__ void ldsm_x4(uint32_t* r, uint32_t addr) {
    asm volatile("ldmatrix.sync.aligned.m8n8.x4.shared.b16 {%0,%1,%2,%3}, [%4];"
                 : "=r"(r[0]), "=r"(r[1]), "=r"(r[2]), "=r"(r[3]) : "r"(addr));
}
__device__ __forceinline__ void ldsm_x2(uint32_t* r, uint32_t addr) {
    asm volatile("ldmatrix.sync.aligned.m8n8.x2.shared.b16 {%0,%1}, [%2];"
                 : "=r"(r[0]), "=r"(r[1]) : "r"(addr));
}
__device__ __forceinline__ void ldsm_x4_t(uint32_t* r, uint32_t addr) {
    asm volatile("ldmatrix.sync.aligned.m8n8.x4.trans.shared.b16 {%0,%1,%2,%3}, [%4];"
                 : "=r"(r[0]), "=r"(r[1]), "=r"(r[2]), "=r"(r[3]) : "r"(addr));
}
__device__ __forceinline__ void mma_bf16(float* c, const uint32_t* a, const uint32_t* b) {
    asm volatile("mma.sync.aligned.m16n8k16.row.col.f32.bf16.bf16.f32 "
                 "{%0,%1,%2,%3}, {%4,%5,%6,%7}, {%8,%9}, {%0,%1,%2,%3};"
                 : "+f"(c[0]), "+f"(c[1]), "+f"(c[2]), "+f"(c[3])
                 : "r"(a[0]), "r"(a[1]), "r"(a[2]), "r"(a[3]), "r"(b[0]), "r"(b[1]));
}
__device__ __forceinline__ void cp16(uint32_t dst, const void* src) {
    asm volatile("cp.async.cg.shared.global [%0], [%1], 16;"
                 :: "r"(dst), "l"(__cvta_generic_to_global(src)) : "memory");
}
__device__ __forceinline__ uint32_t pack2(float a, float b) {
    return (uint32_t)__bfloat16_as_ushort(__float2bfloat16(a)) |
           ((uint32_t)__bfloat16_as_ushort(__float2bfloat16(b)) << 16);
}

// ---------------------------------------------------------------------------
// Prep: split fp32 -> bf16 hi + lo
// ---------------------------------------------------------------------------
__global__ __launch_bounds__(256)
void split_x(const float4* __restrict__ x)
{
    size_t i = (size_t)blockIdx.x * 256 + threadIdx.x;
    float4 v = x[i];
    float h0 = __bfloat162float(__float2bfloat16(v.x));
    float h1 = __bfloat162float(__float2bfloat16(v.y));
    float h2 = __bfloat162float(__float2bfloat16(v.z));
    float h3 = __bfloat162float(__float2bfloat16(v.w));
    uint2 uh, ul;
    uh.x = pack2(v.x, v.y);  uh.y = pack2(v.z, v.w);
    ul.x = pack2(v.x - h0, v.y - h1);
    ul.y = pack2(v.z - h2, v.w - h3);
    ((uint2*)g_xhi)[i] = uh;
    ((uint2*)g_xlo)[i] = ul;
}

__global__ __launch_bounds__(256)
void split_w(const float* __restrict__ Wq, const float* __restrict__ Wk,
             const float* __restrict__ Wv)
{
    size_t i = (size_t)blockIdx.x * 256 + threadIdx.x;
    size_t e = i * 4;
    int r = (int)(e >> 9);
    int c = (int)(e & 511);
    const float* W = (r < 512) ? Wq : (r < 1024) ? Wk : Wv;
    float4 v = *(const float4*)(W + (size_t)(r & 511) * Cn + c);
    float h0 = __bfloat162float(__float2bfloat16(v.x));
    float h1 = __bfloat162float(__float2bfloat16(v.y));
    float h2 = __bfloat162float(__float2bfloat16(v.z));
    float h3 = __bfloat162float(__float2bfloat16(v.w));
    uint2 uh, ul;
    uh.x = pack2(v.x, v.y);  uh.y = pack2(v.z, v.w);
    ul.x = pack2(v.x - h0, v.y - h1);
    ul.y = pack2(v.z - h2, v.w - h3);
    ((uint2*)g_whi)[i] = uh;
    ((uint2*)g_wlo)[i] = ul;
}

// ---------------------------------------------------------------------------
// QKV GEMM: 3-term split-bf16 mma.sync, 3-stage cp.async pipeline,
// one __syncthreads per K-chunk. Epilogue writes q/k/v as bf16 hi/lo pairs
// in [B,W,H,C] layout.
// ---------------------------------------------------------------------------
#define KCH 32
#define NCHUNK (Cn / KCH)         /* 16 */
#define TILE_B 10240              /* 128*40 bf16 = 80B-stride tile */
#define STG_B  (4 * TILE_B)       /* Ahi Alo Bhi Blo */
#define NSTAGE 3

__global__ __launch_bounds__(256, 1)
void qkv_mma()
{
    extern __shared__ char sm[];
    const uint32_t sb = smem_u32(sm);
    const int tid  = threadIdx.x;
    const int wid  = tid >> 5, lane = tid & 31;
    const int m0   = blockIdx.y * 128;
    const int n0g  = blockIdx.x * 128;

    const int warp_m = (wid >> 2) * 64;
    const int warp_n = (wid & 3) * 32;

    const __nv_bfloat16* xa_hi = g_xhi + (size_t)m0 * Cn;
    const __nv_bfloat16* xa_lo = g_xlo + (size_t)m0 * Cn;
    const __nv_bfloat16* wb_hi = g_whi + (size_t)n0g * Cn;
    const __nv_bfloat16* wb_lo = g_wlo + (size_t)n0g * Cn;

    auto load_chunk = [&](int s, int k0) {
        const uint32_t stg = sb + s * STG_B;
#pragma unroll
        for (int t = 0; t < 2; t++) {
            const int idx = tid + t * 256;
            const int row = idx >> 2, seg = idx & 3;
            const uint32_t doff = (uint32_t)(row * 80 + seg * 16);
            const size_t goff = (size_t)row * Cn + k0 + seg * 8;
            cp16(stg + doff,              xa_hi + goff);
            cp16(stg + 2*TILE_B + doff,   wb_hi + goff);
            cp16(stg + TILE_B + doff,     xa_lo + goff);
            cp16(stg + 3*TILE_B + doff,   wb_lo + goff);
        }
        asm volatile("cp.async.commit_group;" ::: "memory");
    };

    float acc[4][4][4];
#pragma unroll
    for (int i = 0; i < 4; i++)
#pragma unroll
        for (int j = 0; j < 4; j++)
#pragma unroll
            for (int q = 0; q < 4; q++) acc[i][j][q] = 0.f;

    const uint32_t a_lane = (uint32_t)((lane & 15) * 80 + (lane >> 4) * 16);
    const uint32_t b_lane = (uint32_t)((lane & 7) * 80 + ((lane >> 3) & 1) * 16);

    load_chunk(0, 0);
    load_chunk(1, KCH);

    for (int k = 0; k < NCHUNK; k++) {
        if (k + 1 < NCHUNK) asm volatile("cp.async.wait_group 1;" ::: "memory");
        else                asm volatile("cp.async.wait_group 0;" ::: "memory");
        __syncthreads();
        if (k + 2 < NCHUNK) load_chunk((k + 2) % NSTAGE, (k + 2) * KCH);

        const uint32_t stg = sb + (k % NSTAGE) * STG_B;
        const uint32_t a_hi_base = stg            + warp_m * 80 + a_lane;
        const uint32_t a_lo_base = stg + TILE_B   + warp_m * 80 + a_lane;
        const uint32_t b_hi_base = stg + 2*TILE_B + warp_n * 80 + b_lane;
        const uint32_t b_lo_base = stg + 3*TILE_B + warp_n * 80 + b_lane;

#pragma unroll
        for (int ks = 0; ks < 2; ks++) {
            uint32_t ah[4][4], bh[4][2];
#pragma unroll
            for (int mf = 0; mf < 4; mf++)
                ldsm_x4(ah[mf], a_hi_base + mf * (16 * 80) + ks * 32);
#pragma unroll
            for (int nf = 0; nf < 4; nf++)
                ldsm_x2(bh[nf], b_hi_base + nf * (8 * 80) + ks * 32);
#pragma unroll
            for (int mf = 0; mf < 4; mf++)
#pragma unroll
                for (int nf = 0; nf < 4; nf++)
                    mma_bf16(acc[mf][nf], ah[mf], bh[nf]);

            uint32_t bl[4][2];
#pragma unroll
            for (int nf = 0; nf < 4; nf++)
                ldsm_x2(bl[nf], b_lo_base + nf * (8 * 80) + ks * 32);
#pragma unroll
            for (int mf = 0; mf < 4; mf++)
#pragma unroll
                for (int nf = 0; nf < 4; nf++)
                    mma_bf16(acc[mf][nf], ah[mf], bl[nf]);

            uint32_t al[4][4];
#pragma unroll
            for (int mf = 0; mf < 4; mf++)
                ldsm_x4(al[mf], a_lo_base + mf * (16 * 80) + ks * 32);
#pragma unroll
            for (int mf = 0; mf < 4; mf++)
#pragma unroll
                for (int nf = 0; nf < 4; nf++)
                    mma_bf16(acc[mf][nf], al[mf], bh[nf]);
        }
    }

    // epilogue: split fp32 acc into bf16 hi/lo, scatter [B,W,H,C]
    const int b  = m0 >> 14;
    const int h  = (m0 >> 7) & 127;
    const int which = n0g >> 9;
    const int col0  = (n0g & 511) + warp_n;
    __nv_bfloat16 *dh, *dl;
    if (which == 0)      { dh = g_qh; dl = g_ql; }
    else if (which == 1) { dh = g_kh; dl = g_kl; }
    else                 { dh = g_vh; dl = g_vl; }

    const int g   = lane >> 2;
    const int c2i = (lane & 3) * 2;
#pragma unroll
    for (int mf = 0; mf < 4; mf++) {
        const int w0 = warp_m + mf * 16 + g;
        const size_t r0 = ((size_t)(b * Wn + w0)     * Hn + h) * Cn + col0 + c2i;
        const size_t r1 = ((size_t)(b * Wn + w0 + 8) * Hn + h) * Cn + col0 + c2i;
#pragma unroll
        for (int nf = 0; nf < 4; nf++) {
            float e0 = acc[mf][nf][0], e1 = acc[mf][nf][1];
            float e2 = acc[mf][nf][2], e3 = acc[mf][nf][3];
            float h0 = __bfloat162float(__float2bfloat16(e0));
            float h1 = __bfloat162float(__float2bfloat16(e1));
            float h2 = __bfloat162float(__float2bfloat16(e2));
            float h3 = __bfloat162float(__float2bfloat16(e3));
            *(uint32_t*)(dh + r0 + nf * 8) = pack2(e0, e1);
            *(uint32_t*)(dl + r0 + nf * 8) = pack2(e0 - h0, e1 - h1);
            *(uint32_t*)(dh + r1 + nf * 8) = pack2(e2, e3);
            *(uint32_t*)(dl + r1 + nf * 8) = pack2(e2 - h2, e3 - h3);
        }
    }
}

// ---------------------------------------------------------------------------
// cc_attn: per-(b,w) column attention, fully tensor-core.
//  Phase 1: E = QK^T, 3-term split mma, 3-stage pipeline. E -> smem fp32 (diag=-inf).
//  Softmax fp32 -> A written as bf16 hi/lo (stride 136).
//  Phase 2: out = gamma*(A@V) + x; V via ldmatrix.trans, 3 terms, 16 c-chunks.
// Smem: [0,123K) stages -> [0,64K) E -> [0,60K) V stages; A at [64K,132K).
// ---------------------------------------------------------------------------
#define A_OFF   65536
#define A_LO_OFF (65536 + 34816)
#define VST_B   20480            /* V chunk: hi 10240 + lo 10240 */
#define CC_SMEM 135168

__global__ __launch_bounds__(256, 1)
void cc_attn(const float* __restrict__ x, const float* __restrict__ gamma_p,
             float* __restrict__ out)
{
    extern __shared__ char sm[];
    const uint32_t sb = smem_u32(sm);
    float* E = (float*)sm;
    __nv_bfloat16* Ahi = (__nv_bfloat16*)(sm + A_OFF);
    __nv_bfloat16* Alo = (__nv_bfloat16*)(sm + A_LO_OFF);

    const int bw  = blockIdx.x;
    const int b   = bw >> 7;
    const int w   = bw & 127;
    const int tid = threadIdx.x;
    const int wid = tid >> 5, lane = tid & 31;

    const size_t colbase = (size_t)bw * (Hn * Cn);
    const __nv_bfloat16* qh = g_qh + colbase;
    const __nv_bfloat16* ql = g_ql + colbase;
    const __nv_bfloat16* kh = g_kh + colbase;
    const __nv_bfloat16* kl = g_kl + colbase;
    const __nv_bfloat16* vh = g_vh + colbase;
    const __nv_bfloat16* vl = g_vl + colbase;

    // ---------------- Phase 1: E = Q K^T ----------------
    const int warp_m = (wid >> 2) * 64;
    const int warp_n = (wid & 3) * 32;

    auto load_chunk = [&](int s, int k0) {
        const uint32_t stg = sb + s * STG_B;
#pragma unroll
        for (int t = 0; t < 2; t++) {
            const int idx = tid + t * 256;
            const int row = idx >> 2, seg = idx & 3;
            const uint32_t doff = (uint32_t)(row * 80 + seg * 16);
            const size_t goff = (size_t)row * Cn + k0 + seg * 8;
            cp16(stg + doff,              qh + goff);
            cp16(stg + 2*TILE_B + doff,   kh + goff);
            cp16(stg + TILE_B + doff,     ql + goff);
            cp16(stg + 3*TILE_B + doff,   kl + goff);
        }
        asm volatile("cp.async.commit_group;" ::: "memory");
    };

    float acc[4][4][4];
#pragma unroll
    for (int i = 0; i < 4; i++)
#pragma unroll
        for (int j = 0; j < 4; j++)
#pragma unroll
            for (int q = 0; q < 4; q++) acc[i][j][q] = 0.f;

    const uint32_t a_lane = (uint32_t)((lane & 15) * 80 + (lane >> 4) * 16);
    const uint32_t b_lane = (uint32_t)((lane & 7) * 80 + ((lane >> 3) & 1) * 16);

    load_chunk(0, 0);
    load_chunk(1, KCH);

    for (int k = 0; k < NCHUNK; k++) {
        if (k + 1 < NCHUNK) asm volatile("cp.async.wait_group 1;" ::: "memory");
        else                asm volatile("cp.async.wait_group 0;" ::: "memory");
        __syncthreads();
        if (k + 2 < NCHUNK) load_chunk((k + 2) % NSTAGE, (k + 2) * KCH);

        const uint32_t stg = sb + (k % NSTAGE) * STG_B;
        const uint32_t a_hi_base = stg            + warp_m * 80 + a_lane;
        const uint32_t a_lo_base = stg + TILE_B   + warp_m * 80 + a_lane;
        const uint32_t b_hi_base = stg + 2*TILE_B + warp_n * 80 + b_lane;
        const uint32_t b_lo_base = stg + 3*TILE_B + warp_n * 80 + b_lane;

#pragma unroll
        for (int ks = 0; ks < 2; ks++) {
            uint32_t ah[4][4], bh[4][2];
#pragma unroll
            for (int mf = 0; mf < 4; mf++)
                ldsm_x4(ah[mf], a_hi_base + mf * (16 * 80) + ks * 32);
#pragma unroll
            for (int nf = 0; nf < 4; nf++)
                ldsm_x2(bh[nf], b_hi_base + nf * (8 * 80) + ks * 32);
#pragma unroll
            for (int mf = 0; mf < 4; mf++)
#pragma unroll
                for (int nf = 0; nf < 4; nf++)
                    mma_bf16(acc[mf][nf], ah[mf], bh[nf]);

            uint32_t bl[4][2];
#pragma unroll
            for (int nf = 0; nf < 4; nf++)
                ldsm_x2(bl[nf], b_lo_base + nf * (8 * 80) + ks * 32);
#pragma unroll
            for (int mf = 0; mf < 4; mf++)
#pragma unroll
                for (int nf = 0; nf < 4; nf++)
                    mma_bf16(acc[mf][nf], ah[mf], bl[nf]);

            uint32_t al[4][4];
#pragma unroll
            for (int mf = 0; mf < 4; mf++)
                ldsm_x4(al[mf], a_lo_base + mf * (16 * 80) + ks * 32);
#pragma unroll
            for (int mf = 0; mf < 4; mf++)
#pragma unroll
                for (int nf = 0; nf < 4; nf++)
                    mma_bf16(acc[mf][nf], al[mf], bh[nf]);
        }
    }
    __syncthreads();   // all stage reads done before E overlays stages

    // write E (fp32) with diagonal = -inf
    const float NEG_INF = __int_as_float(0xff800000);
    {
        const int gr  = lane >> 2;
        const int c2i = (lane & 3) * 2;
#pragma unroll
        for (int mf = 0; mf < 4; mf++) {
            const int h0r = warp_m + mf * 16 + gr;
            const int h1r = h0r + 8;
#pragma unroll
            for (int nf = 0; nf < 4; nf++) {
                const int gg = warp_n + nf * 8 + c2i;
                E[h0r * 128 + gg    ] = (h0r == gg    ) ? NEG_INF : acc[mf][nf][0];
                E[h0r * 128 + gg + 1] = (h0r == gg + 1) ? NEG_INF : acc[mf][nf][1];
                E[h1r * 128 + gg    ] = (h1r == gg    ) ? NEG_INF : acc[mf][nf][2];
                E[h1r * 128 + gg + 1] = (h1r == gg + 1) ? NEG_INF : acc[mf][nf][3];
            }
        }
    }
    __syncthreads();

    // softmax over g; write A as bf16 hi/lo at stride 136
    for (int r = wid; r < 128; r += 8) {
        float* row = E + r * 128;
        float v0 = row[lane], v1 = row[lane + 32], v2 = row[lane + 64], v3 = row[lane + 96];
        float mx = fmaxf(fmaxf(v0, v1), fmaxf(v2, v3));
#pragma unroll
        for (int o = 16; o > 0; o >>= 1) mx = fmaxf(mx, __shfl_xor_sync(0xffffffffu, mx, o));
        v0 = __expf(v0 - mx); v1 = __expf(v1 - mx);
        v2 = __expf(v2 - mx); v3 = __expf(v3 - mx);
        float s = v0 + v1 + v2 + v3;
#pragma unroll
        for (int o = 16; o > 0; o >>= 1) s += __shfl_xor_sync(0xffffffffu, s, o);
        const float inv = 1.f / s;
        float p[4] = {v0 * inv, v1 * inv, v2 * inv, v3 * inv};
#pragma unroll
        for (int j = 0; j < 4; j++) {
            const int gg = lane + j * 32;
            __nv_bfloat16 hi = __float2bfloat16(p[j]);
            Ahi[r * 136 + gg] = hi;
            Alo[r * 136 + gg] = __float2bfloat16(p[j] - __bfloat162float(hi));
        }
    }
    __syncthreads();   // E dead; A ready

    // ---------------- Phase 2: out = gamma * (A @ V) + x ----------------
    auto loadV = [&](int s, int ci) {
        const uint32_t stg = sb + s * VST_B;
        const int c0 = ci * 32;
#pragma unroll
        for (int t = 0; t < 2; t++) {
            const int idx = tid + t * 256;
            const int row = idx >> 2, seg = idx & 3;
            const uint32_t doff = (uint32_t)(row * 80 + seg * 16);
            const size_t goff = (size_t)row * Cn + c0 + seg * 8;
            cp16(stg + doff,         vh + goff);
            cp16(stg + 10240 + doff, vl + goff);
        }
        asm volatile("cp.async.commit_group;" ::: "memory");
    };

    loadV(0, 0);
    loadV(1, 1);

    // persistent A fragments: warp owns 16 h-rows
    const int h0 = wid * 16;
    uint32_t Ah[8][4], Al[8][4];
    {
        const uint32_t abase = sb + A_OFF +
            (uint32_t)(((h0 + (lane & 15)) * 136 + (lane >> 4) * 8) * 2);
#pragma unroll
        for (int ks = 0; ks < 8; ks++) {
            ldsm_x4(Ah[ks], abase + ks * 32);
            ldsm_x4(Al[ks], abase + (A_LO_OFF - A_OFF) + ks * 32);
        }
    }

    const float gam = gamma_p[0];
    const uint32_t v_lane = (uint32_t)(((lane & 7) + ((lane >> 3) & 1) * 8) * 80 +
                                       (lane >> 4) * 16);

    for (int ci = 0; ci < 16; ci++) {
        if (ci + 1 < 16) asm volatile("cp.async.wait_group 1;" ::: "memory");
        else             asm volatile("cp.async.wait_group 0;" ::: "memory");
        __syncthreads();
        if (ci + 2 < 16) loadV((ci + 2) % 3, ci + 2);

        const uint32_t vs = sb + (ci % 3) * VST_B;

        float acc2[4][4];
#pragma unroll
        for (int j = 0; j < 4; j++)
#pragma unroll
            for (int q = 0; q < 4; q++) acc2[j][q] = 0.f;

#pragma unroll
        for (int ks = 0; ks < 8; ks++) {
            const uint32_t vrow = vs + (uint32_t)(ks * 16 * 80) + v_lane;
            uint32_t bh0[4], bh1[4], bl0[4], bl1[4];
            ldsm_x4_t(bh0, vrow);                 // c 0..15 (hi)
            ldsm_x4_t(bh1, vrow + 32);            // c 16..31 (hi)
            ldsm_x4_t(bl0, vrow + 10240);         // lo
            ldsm_x4_t(bl1, vrow + 10240 + 32);
            mma_bf16(acc2[0], Ah[ks], bh0);
            mma_bf16(acc2[1], Ah[ks], bh0 + 2);
            mma_bf16(acc2[2], Ah[ks], bh1);
            mma_bf16(acc2[3], Ah[ks], bh1 + 2);
            mma_bf16(acc2[0], Ah[ks], bl0);
            mma_bf16(acc2[1], Ah[ks], bl0 + 2);
            mma_bf16(acc2[2], Ah[ks], bl1);
            mma_bf16(acc2[3], Ah[ks], bl1 + 2);
            mma_bf16(acc2[0], Al[ks], bh0);
            mma_bf16(acc2[1], Al[ks], bh0 + 2);
            mma_bf16(acc2[2], Al[ks], bh1);
            mma_bf16(acc2[3], Al[ks], bh1 + 2);
        }

        // write chunk: gamma * acc + x
        const int hr = h0 + (lane >> 2);
#pragma unroll
        for (int j = 0; j < 4; j++) {
            const int c = ci * 32 + j * 8 + (lane & 3) * 2;
            const size_t o0 = ((size_t)(b * Hn + hr)     * Wn + w) * Cn + c;
            const size_t o1 = ((size_t)(b * Hn + hr + 8) * Wn + w) * Cn + c;
            float2 x0 = *(const float2*)(x + o0);
            float2 x1 = *(const float2*)(x + o1);
            float2 r0, r1;
            r0.x = fmaf(gam, acc2[j][0], x0.x);
            r0.y = fmaf(gam, acc2[j][1], x0.y);
            r1.x = fmaf(gam, acc2[j][2], x1.x);
            r1.y = fmaf(gam, acc2[j][3], x1.y);
            *(float2*)(out + o0) = r0;
            *(float2*)(out + o1) = r1;
        }
    }
}

// ---------------------------------------------------------------------------
extern "C" void kernel_launch(void* const* d_in, const int* in_sizes, int n_in,
                              void* d_out, int out_size)
{
    const float* x  = (const float*)d_in[0];
    const float* Wq = (const float*)d_in[1];
    const float* Wk = (const float*)d_in[2];
    const float* Wv = (const float*)d_in[3];
    const float* gm = (const float*)d_in[4];
    float* out = (float*)d_out;

    split_x<<<(size_t)MTOT * Cn / 4 / 256, 256>>>((const float4*)x);
    split_w<<<(size_t)NTOT * Cn / 4 / 256, 256>>>(Wq, Wk, Wv);

    const int gemm_smem = NSTAGE * STG_B;   // 122880
    cudaFuncSetAttribute(qkv_mma, cudaFuncAttributeMaxDynamicSharedMemorySize, gemm_smem);
    dim3 grid_g(NTOT / 128, MTOT / 128);    // (12, 1024)
    qkv_mma<<<grid_g, 256, gemm_smem>>>();

    cudaFuncSetAttribute(cc_attn, cudaFuncAttributeMaxDynamicSharedMemorySize, CC_SMEM);
    cc_attn<<<NCOL, 256, CC_SMEM>>>(x, gm, out);
}

// round 6
// speedup vs baseline: 2.8112x; 1.4653x over previous
#include <cuda_runtime.h>
#include <cuda_bf16.h>
#include <cuda_fp16.h>
#include <cstdint>

#define Bn 8
#define Hn 128
#define Wn 128
#define Cn 512
#define NCOL (Bn*Wn)          /* 1024 (b,w) columns */
#define MTOT (Bn*Hn*Wn)       /* 131072 rows for QKV GEMM */

// bf16 hi/lo splits of x (for high-precision q,k projection)
__device__ __nv_bfloat16 g_xhi[(size_t)MTOT * Cn];
__device__ __nv_bfloat16 g_xlo[(size_t)MTOT * Cn];
// fp16 single of x (for V projection)
__device__ __half        g_x16[(size_t)MTOT * Cn];
// weights: [Wq;Wk] bf16 hi/lo (1024 rows), Wv fp16 single (512 rows)
__device__ __nv_bfloat16 g_whi[(size_t)1024 * Cn];
__device__ __nv_bfloat16 g_wlo[(size_t)1024 * Cn];
__device__ __half        g_wv16[(size_t)512 * Cn];
// q,k fp16 hi/lo pairs, v fp16 single; all [B,W,H,C]
__device__ __half g_qh[(size_t)NCOL * Hn * Cn];
__device__ __half g_ql[(size_t)NCOL * Hn * Cn];
__device__ __half g_kh[(size_t)NCOL * Hn * Cn];
__device__ __half g_kl[(size_t)NCOL * Hn * Cn];
__device__ __half g_v16[(size_t)NCOL * Hn * Cn];

__device__ __forceinline__ uint32_t smem_u32(const void* p) {
    uint32_t a;
    asm("{ .reg .u64 t; cvta.to.shared.u64 t, %1; cvt.u32.u64 %0, t; }" : "=r"(a) : "l"(p));
    return a;
}
__device__ __forceinline__ void ldsm_x4(uint32_t* r, uint32_t addr) {
    asm volatile("ldmatrix.sync.aligned.m8n8.x4.shared.b16 {%0,%1,%2,%3}, [%4];"
                 : "=r"(r[0]), "=r"(r[1]), "=r"(r[2]), "=r"(r[3]) : "r"(addr));
}
__device__ __forceinline__ void ldsm_x2(uint32_t* r, uint32_t addr) {
    asm volatile("ldmatrix.sync.aligned.m8n8.x2.shared.b16 {%0,%1}, [%2];"
                 : "=r"(r[0]), "=r"(r[1]) : "r"(addr));
}
__device__ __forceinline__ void ldsm_x4_t(uint32_t* r, uint32_t addr) {
    asm volatile("ldmatrix.sync.aligned.m8n8.x4.trans.shared.b16 {%0,%1,%2,%3}, [%4];"
                 : "=r"(r[0]), "=r"(r[1]), "=r"(r[2]), "=r"(r[3]) : "r"(addr));
}
__device__ __forceinline__ void mma_bf16(float* c, const uint32_t* a, const uint32_t* b) {
    asm volatile("mma.sync.aligned.m16n8k16.row.col.f32.bf16.bf16.f32 "
                 "{%0,%1,%2,%3}, {%4,%5,%6,%7}, {%8,%9}, {%0,%1,%2,%3};"
                 : "+f"(c[0]), "+f"(c[1]), "+f"(c[2]), "+f"(c[3])
                 : "r"(a[0]), "r"(a[1]), "r"(a[2]), "r"(a[3]), "r"(b[0]), "r"(b[1]));
}
__device__ __forceinline__ void mma_f16(float* c, const uint32_t* a, const uint32_t* b) {
    asm volatile("mma.sync.aligned.m16n8k16.row.col.f32.f16.f16.f32 "
                 "{%0,%1,%2,%3}, {%4,%5,%6,%7}, {%8,%9}, {%0,%1,%2,%3};"
                 : "+f"(c[0]), "+f"(c[1]), "+f"(c[2]), "+f"(c[3])
                 : "r"(a[0]), "r"(a[1]), "r"(a[2]), "r"(a[3]), "r"(b[0]), "r"(b[1]));
}
__device__ __forceinline__ void cp16(uint32_t dst, const void* src) {
    asm volatile("cp.async.cg.shared.global [%0], [%1], 16;"
                 :: "r"(dst), "l"(__cvta_generic_to_global(src)) : "memory");
}
__device__ __forceinline__ uint32_t pack2b(float a, float b) {
    return (uint32_t)__bfloat16_as_ushort(__float2bfloat16(a)) |
           ((uint32_t)__bfloat16_as_ushort(__float2bfloat16(b)) << 16);
}
__device__ __forceinline__ uint32_t pack2h(float a, float b) {
    __half2 h = __floats2half2_rn(a, b);
    return *(uint32_t*)&h;
}

// ---------------------------------------------------------------------------
// Prep: x -> bf16 hi/lo + fp16 single;  W -> [Wq;Wk] bf16 hi/lo, Wv fp16
// ---------------------------------------------------------------------------
__global__ __launch_bounds__(256)
void split_x(const float4* __restrict__ x)
{
    size_t i = (size_t)blockIdx.x * 256 + threadIdx.x;
    float4 v = x[i];
    float h0 = __bfloat162float(__float2bfloat16(v.x));
    float h1 = __bfloat162float(__float2bfloat16(v.y));
    float h2 = __bfloat162float(__float2bfloat16(v.z));
    float h3 = __bfloat162float(__float2bfloat16(v.w));
    uint2 uh, ul, uf;
    uh.x = pack2b(v.x, v.y);  uh.y = pack2b(v.z, v.w);
    ul.x = pack2b(v.x - h0, v.y - h1);
    ul.y = pack2b(v.z - h2, v.w - h3);
    uf.x = pack2h(v.x, v.y);  uf.y = pack2h(v.z, v.w);
    ((uint2*)g_xhi)[i] = uh;
    ((uint2*)g_xlo)[i] = ul;
    ((uint2*)g_x16)[i] = uf;
}

__global__ __launch_bounds__(256)
void split_w(const float* __restrict__ Wq, const float* __restrict__ Wk,
             const float* __restrict__ Wv)
{
    size_t i = (size_t)blockIdx.x * 256 + threadIdx.x;   // over 1536*512/4
    size_t e = i * 4;
    int r = (int)(e >> 9);
    int c = (int)(e & 511);
    if (r < 1024) {
        const float* W = (r < 512) ? Wq : Wk;
        float4 v = *(const float4*)(W + (size_t)(r & 511) * Cn + c);
        float h0 = __bfloat162float(__float2bfloat16(v.x));
        float h1 = __bfloat162float(__float2bfloat16(v.y));
        float h2 = __bfloat162float(__float2bfloat16(v.z));
        float h3 = __bfloat162float(__float2bfloat16(v.w));
        uint2 uh, ul;
        uh.x = pack2b(v.x, v.y);  uh.y = pack2b(v.z, v.w);
        ul.x = pack2b(v.x - h0, v.y - h1);
        ul.y = pack2b(v.z - h2, v.w - h3);
        ((uint2*)g_whi)[i] = uh;
        ((uint2*)g_wlo)[i] = ul;
    } else {
        float4 v = *(const float4*)(Wv + (size_t)(r - 1024) * Cn + c);
        uint2 uf;
        uf.x = pack2h(v.x, v.y);  uf.y = pack2h(v.z, v.w);
        ((uint2*)g_wv16)[i - 131072] = uf;
    }
}

// ---------------------------------------------------------------------------
// QK projection GEMM: 3-term split-bf16, 2-stage pipeline (R4-proven),
// 2 CTAs/SM. Epilogue writes q/k as fp16 hi/lo in [B,W,H,C].
// ---------------------------------------------------------------------------
#define KCH 32
#define NCHUNK (Cn / KCH)         /* 16 */
#define TILE_B 10240              /* 128 rows x 80B */
#define STG_B  (4 * TILE_B)

__global__ __launch_bounds__(256, 2)
void qk_mma()
{
    extern __shared__ char sm[];
    const uint32_t sb = smem_u32(sm);
    const int tid  = threadIdx.x;
    const int wid  = tid >> 5, lane = tid & 31;
    const int m0   = blockIdx.y * 128;
    const int n0g  = blockIdx.x * 128;      // 0..1023 (q|k)

    const int warp_m = (wid >> 2) * 64;
    const int warp_n = (wid & 3) * 32;

    const __nv_bfloat16* xa_hi = g_xhi + (size_t)m0 * Cn;
    const __nv_bfloat16* xa_lo = g_xlo + (size_t)m0 * Cn;
    const __nv_bfloat16* wb_hi = g_whi + (size_t)n0g * Cn;
    const __nv_bfloat16* wb_lo = g_wlo + (size_t)n0g * Cn;

    auto load_chunk = [&](int s, int k0) {
        const uint32_t stg = sb + s * STG_B;
#pragma unroll
        for (int t = 0; t < 2; t++) {
            const int idx = tid + t * 256;
            const int row = idx >> 2, seg = idx & 3;
            const uint32_t doff = (uint32_t)(row * 80 + seg * 16);
            const size_t goff = (size_t)row * Cn + k0 + seg * 8;
            cp16(stg + doff,              xa_hi + goff);
            cp16(stg + 2*TILE_B + doff,   wb_hi + goff);
            cp16(stg + TILE_B + doff,     xa_lo + goff);
            cp16(stg + 3*TILE_B + doff,   wb_lo + goff);
        }
        asm volatile("cp.async.commit_group;" ::: "memory");
    };

    float acc[4][4][4];
#pragma unroll
    for (int i = 0; i < 4; i++)
#pragma unroll
        for (int j = 0; j < 4; j++)
#pragma unroll
            for (int q = 0; q < 4; q++) acc[i][j][q] = 0.f;

    const uint32_t a_lane = (uint32_t)((lane & 15) * 80 + (lane >> 4) * 16);
    const uint32_t b_lane = (uint32_t)((lane & 7) * 80 + ((lane >> 3) & 1) * 16);

    load_chunk(0, 0);
    load_chunk(1, KCH);

    for (int k = 0; k < NCHUNK; k++) {
        const int s = k & 1;
        const uint32_t stg = sb + s * STG_B;

        if (k < NCHUNK - 2) asm volatile("cp.async.wait_group 1;" ::: "memory");
        else                asm volatile("cp.async.wait_group 0;" ::: "memory");
        __syncthreads();

        const uint32_t a_hi_base = stg            + warp_m * 80 + a_lane;
        const uint32_t a_lo_base = stg + TILE_B   + warp_m * 80 + a_lane;
        const uint32_t b_hi_base = stg + 2*TILE_B + warp_n * 80 + b_lane;
        const uint32_t b_lo_base = stg + 3*TILE_B + warp_n * 80 + b_lane;

#pragma unroll
        for (int ks = 0; ks < 2; ks++) {
            uint32_t ah[4][4], bh[4][2];
#pragma unroll
            for (int mf = 0; mf < 4; mf++)
                ldsm_x4(ah[mf], a_hi_base + mf * (16 * 80) + ks * 32);
#pragma unroll
            for (int nf = 0; nf < 4; nf++)
                ldsm_x2(bh[nf], b_hi_base + nf * (8 * 80) + ks * 32);
#pragma unroll
            for (int mf = 0; mf < 4; mf++)
#pragma unroll
                for (int nf = 0; nf < 4; nf++)
                    mma_bf16(acc[mf][nf], ah[mf], bh[nf]);

            uint32_t bl[4][2];
#pragma unroll
            for (int nf = 0; nf < 4; nf++)
                ldsm_x2(bl[nf], b_lo_base + nf * (8 * 80) + ks * 32);
#pragma unroll
            for (int mf = 0; mf < 4; mf++)
#pragma unroll
                for (int nf = 0; nf < 4; nf++)
                    mma_bf16(acc[mf][nf], ah[mf], bl[nf]);

            uint32_t al[4][4];
#pragma unroll
            for (int mf = 0; mf < 4; mf++)
                ldsm_x4(al[mf], a_lo_base + mf * (16 * 80) + ks * 32);
#pragma unroll
            for (int mf = 0; mf < 4; mf++)
#pragma unroll
                for (int nf = 0; nf < 4; nf++)
                    mma_bf16(acc[mf][nf], al[mf], bh[nf]);
        }
        __syncthreads();

        if (k + 2 < NCHUNK) load_chunk(s, (k + 2) * KCH);
    }

    // epilogue: fp16 hi/lo, scatter [B,W,H,C]
    const int b  = m0 >> 14;
    const int h  = (m0 >> 7) & 127;
    const int which = n0g >> 9;
    const int col0  = (n0g & 511) + warp_n;
    __half *dh = which ? g_kh : g_qh;
    __half *dl = which ? g_kl : g_ql;

    const int g   = lane >> 2;
    const int c2i = (lane & 3) * 2;
#pragma unroll
    for (int mf = 0; mf < 4; mf++) {
        const int w0 = warp_m + mf * 16 + g;
        const size_t r0 = ((size_t)(b * Wn + w0)     * Hn + h) * Cn + col0 + c2i;
        const size_t r1 = ((size_t)(b * Wn + w0 + 8) * Hn + h) * Cn + col0 + c2i;
#pragma unroll
        for (int nf = 0; nf < 4; nf++) {
            float e0 = acc[mf][nf][0], e1 = acc[mf][nf][1];
            float e2 = acc[mf][nf][2], e3 = acc[mf][nf][3];
            float h0 = __half2float(__float2half_rn(e0));
            float h1 = __half2float(__float2half_rn(e1));
            float h2 = __half2float(__float2half_rn(e2));
            float h3 = __half2float(__float2half_rn(e3));
            *(uint32_t*)(dh + r0 + nf * 8) = pack2h(e0, e1);
            *(uint32_t*)(dl + r0 + nf * 8) = pack2h(e0 - h0, e1 - h1);
            *(uint32_t*)(dh + r1 + nf * 8) = pack2h(e2, e3);
            *(uint32_t*)(dl + r1 + nf * 8) = pack2h(e2 - h2, e3 - h3);
        }
    }
}

// ---------------------------------------------------------------------------
// V projection GEMM: single-pass fp16, 2-stage. Output fp16 [B,W,H,C].
// ---------------------------------------------------------------------------
#define VSTG_B (2 * TILE_B)

__global__ __launch_bounds__(256, 2)
void v_mma()
{
    extern __shared__ char sm[];
    const uint32_t sb = smem_u32(sm);
    const int tid  = threadIdx.x;
    const int wid  = tid >> 5, lane = tid & 31;
    const int m0   = blockIdx.y * 128;
    const int n0v  = blockIdx.x * 128;      // 0..511

    const int warp_m = (wid >> 2) * 64;
    const int warp_n = (wid & 3) * 32;

    const __half* xa = g_x16  + (size_t)m0 * Cn;
    const __half* wb = g_wv16 + (size_t)n0v * Cn;

    auto load_chunk = [&](int s, int k0) {
        const uint32_t stg = sb + s * VSTG_B;
#pragma unroll
        for (int t = 0; t < 2; t++) {
            const int idx = tid + t * 256;
            const int row = idx >> 2, seg = idx & 3;
            const uint32_t doff = (uint32_t)(row * 80 + seg * 16);
            const size_t goff = (size_t)row * Cn + k0 + seg * 8;
            cp16(stg + doff,          xa + goff);
            cp16(stg + TILE_B + doff, wb + goff);
        }
        asm volatile("cp.async.commit_group;" ::: "memory");
    };

    float acc[4][4][4];
#pragma unroll
    for (int i = 0; i < 4; i++)
#pragma unroll
        for (int j = 0; j < 4; j++)
#pragma unroll
            for (int q = 0; q < 4; q++) acc[i][j][q] = 0.f;

    const uint32_t a_lane = (uint32_t)((lane & 15) * 80 + (lane >> 4) * 16);
    const uint32_t b_lane = (uint32_t)((lane & 7) * 80 + ((lane >> 3) & 1) * 16);

    load_chunk(0, 0);
    load_chunk(1, KCH);

    for (int k = 0; k < NCHUNK; k++) {
        const int s = k & 1;
        const uint32_t stg = sb + s * VSTG_B;

        if (k < NCHUNK - 2) asm volatile("cp.async.wait_group 1;" ::: "memory");
        else                asm volatile("cp.async.wait_group 0;" ::: "memory");
        __syncthreads();

        const uint32_t a_base = stg          + warp_m * 80 + a_lane;
        const uint32_t b_base = stg + TILE_B + warp_n * 80 + b_lane;

#pragma unroll
        for (int ks = 0; ks < 2; ks++) {
            uint32_t ah[4][4], bh[4][2];
#pragma unroll
            for (int mf = 0; mf < 4; mf++)
                ldsm_x4(ah[mf], a_base + mf * (16 * 80) + ks * 32);
#pragma unroll
            for (int nf = 0; nf < 4; nf++)
                ldsm_x2(bh[nf], b_base + nf * (8 * 80) + ks * 32);
#pragma unroll
            for (int mf = 0; mf < 4; mf++)
#pragma unroll
                for (int nf = 0; nf < 4; nf++)
                    mma_f16(acc[mf][nf], ah[mf], bh[nf]);
        }
        __syncthreads();

        if (k + 2 < NCHUNK) load_chunk(s, (k + 2) * KCH);
    }

    const int b  = m0 >> 14;
    const int h  = (m0 >> 7) & 127;
    const int col0 = n0v + warp_n;
    const int g   = lane >> 2;
    const int c2i = (lane & 3) * 2;
#pragma unroll
    for (int mf = 0; mf < 4; mf++) {
        const int w0 = warp_m + mf * 16 + g;
        const size_t r0 = ((size_t)(b * Wn + w0)     * Hn + h) * Cn + col0 + c2i;
        const size_t r1 = ((size_t)(b * Wn + w0 + 8) * Hn + h) * Cn + col0 + c2i;
#pragma unroll
        for (int nf = 0; nf < 4; nf++) {
            *(uint32_t*)(g_v16 + r0 + nf * 8) = pack2h(acc[mf][nf][0], acc[mf][nf][1]);
            *(uint32_t*)(g_v16 + r1 + nf * 8) = pack2h(acc[mf][nf][2], acc[mf][nf][3]);
        }
    }
}

// ---------------------------------------------------------------------------
// cc_attn: phase 1 = QK^T 3-term fp16 (q fp16 hi/lo, k fp16 hi/lo);
// softmax fp32 -> A fp16 single; phase 2 = AV single-term fp16.
// Smem: phase1 stages [0,80K) -> E fp32 [0,64K) + Ahi [64K,98.8K);
// V 2-stage [0,20K) after softmax. Total 100352 -> 2 CTAs/SM.
// ---------------------------------------------------------------------------
#define A_OFF   65536
#define VST_B   10240
#define CC_SMEM 100352

__global__ __launch_bounds__(256, 2)
void cc_attn(const float* __restrict__ x, const float* __restrict__ gamma_p,
             float* __restrict__ out)
{
    extern __shared__ char sm[];
    const uint32_t sb = smem_u32(sm);
    float* E = (float*)sm;
    __half* Ahi = (__half*)(sm + A_OFF);

    const int bw  = blockIdx.x;
    const int b   = bw >> 7;
    const int w   = bw & 127;
    const int tid = threadIdx.x;
    const int wid = tid >> 5, lane = tid & 31;

    const size_t colbase = (size_t)bw * (Hn * Cn);
    const __half* qh = g_qh + colbase;
    const __half* ql = g_ql + colbase;
    const __half* kh = g_kh + colbase;
    const __half* kl = g_kl + colbase;
    const __half* v16 = g_v16 + colbase;

    // ---------------- Phase 1: E = Q K^T (3-term fp16) ----------------
    const int warp_m = (wid >> 2) * 64;
    const int warp_n = (wid & 3) * 32;

    auto load_chunk = [&](int s, int k0) {
        const uint32_t stg = sb + s * STG_B;
#pragma unroll
        for (int t = 0; t < 2; t++) {
            const int idx = tid + t * 256;
            const int row = idx >> 2, seg = idx & 3;
            const uint32_t doff = (uint32_t)(row * 80 + seg * 16);
            const size_t goff = (size_t)row * Cn + k0 + seg * 8;
            cp16(stg + doff,              qh + goff);
            cp16(stg + 2*TILE_B + doff,   kh + goff);
            cp16(stg + TILE_B + doff,     ql + goff);
            cp16(stg + 3*TILE_B + doff,   kl + goff);
        }
        asm volatile("cp.async.commit_group;" ::: "memory");
    };

    float acc[4][4][4];
#pragma unroll
    for (int i = 0; i < 4; i++)
#pragma unroll
        for (int j = 0; j < 4; j++)
#pragma unroll
            for (int q = 0; q < 4; q++) acc[i][j][q] = 0.f;

    const uint32_t a_lane = (uint32_t)((lane & 15) * 80 + (lane >> 4) * 16);
    const uint32_t b_lane = (uint32_t)((lane & 7) * 80 + ((lane >> 3) & 1) * 16);

    load_chunk(0, 0);
    load_chunk(1, KCH);

    for (int k = 0; k < NCHUNK; k++) {
        const int s = k & 1;
        const uint32_t stg = sb + s * STG_B;

        if (k < NCHUNK - 2) asm volatile("cp.async.wait_group 1;" ::: "memory");
        else                asm volatile("cp.async.wait_group 0;" ::: "memory");
        __syncthreads();

        const uint32_t a_hi_base = stg            + warp_m * 80 + a_lane;
        const uint32_t a_lo_base = stg + TILE_B   + warp_m * 80 + a_lane;
        const uint32_t b_hi_base = stg + 2*TILE_B + warp_n * 80 + b_lane;
        const uint32_t b_lo_base = stg + 3*TILE_B + warp_n * 80 + b_lane;

#pragma unroll
        for (int ks = 0; ks < 2; ks++) {
            uint32_t ah[4][4], bh[4][2];
#pragma unroll
            for (int mf = 0; mf < 4; mf++)
                ldsm_x4(ah[mf], a_hi_base + mf * (16 * 80) + ks * 32);
#pragma unroll
            for (int nf = 0; nf < 4; nf++)
                ldsm_x2(bh[nf], b_hi_base + nf * (8 * 80) + ks * 32);
#pragma unroll
            for (int mf = 0; mf < 4; mf++)
#pragma unroll
                for (int nf = 0; nf < 4; nf++)
                    mma_f16(acc[mf][nf], ah[mf], bh[nf]);

            uint32_t bl[4][2];
#pragma unroll
            for (int nf = 0; nf < 4; nf++)
                ldsm_x2(bl[nf], b_lo_base + nf * (8 * 80) + ks * 32);
#pragma unroll
            for (int mf = 0; mf < 4; mf++)
#pragma unroll
                for (int nf = 0; nf < 4; nf++)
                    mma_f16(acc[mf][nf], ah[mf], bl[nf]);

            uint32_t al[4][4];
#pragma unroll
            for (int mf = 0; mf < 4; mf++)
                ldsm_x4(al[mf], a_lo_base + mf * (16 * 80) + ks * 32);
#pragma unroll
            for (int mf = 0; mf < 4; mf++)
#pragma unroll
                for (int nf = 0; nf < 4; nf++)
                    mma_f16(acc[mf][nf], al[mf], bh[nf]);
        }
        __syncthreads();

        if (k + 2 < NCHUNK) load_chunk(s, (k + 2) * KCH);
    }

    // write E (fp32) with diagonal = -inf (stage region is dead now)
    const float NEG_INF = __int_as_float(0xff800000);
    {
        const int gr  = lane >> 2;
        const int c2i = (lane & 3) * 2;
#pragma unroll
        for (int mf = 0; mf < 4; mf++) {
            const int h0r = warp_m + mf * 16 + gr;
            const int h1r = h0r + 8;
#pragma unroll
            for (int nf = 0; nf < 4; nf++) {
                const int gg = warp_n + nf * 8 + c2i;
                E[h0r * 128 + gg    ] = (h0r == gg    ) ? NEG_INF : acc[mf][nf][0];
                E[h0r * 128 + gg + 1] = (h0r == gg + 1) ? NEG_INF : acc[mf][nf][1];
                E[h1r * 128 + gg    ] = (h1r == gg    ) ? NEG_INF : acc[mf][nf][2];
                E[h1r * 128 + gg + 1] = (h1r == gg + 1) ? NEG_INF : acc[mf][nf][3];
            }
        }
    }
    __syncthreads();

    // softmax over g; write A fp16 at stride 136
    for (int r = wid; r < 128; r += 8) {
        float* row = E + r * 128;
        float v0 = row[lane], v1 = row[lane + 32], v2 = row[lane + 64], v3 = row[lane + 96];
        float mx = fmaxf(fmaxf(v0, v1), fmaxf(v2, v3));
#pragma unroll
        for (int o = 16; o > 0; o >>= 1) mx = fmaxf(mx, __shfl_xor_sync(0xffffffffu, mx, o));
        v0 = __expf(v0 - mx); v1 = __expf(v1 - mx);
        v2 = __expf(v2 - mx); v3 = __expf(v3 - mx);
        float s = v0 + v1 + v2 + v3;
#pragma unroll
        for (int o = 16; o > 0; o >>= 1) s += __shfl_xor_sync(0xffffffffu, s, o);
        const float inv = 1.f / s;
        Ahi[r * 136 + lane     ] = __float2half_rn(v0 * inv);
        Ahi[r * 136 + lane + 32] = __float2half_rn(v1 * inv);
        Ahi[r * 136 + lane + 64] = __float2half_rn(v2 * inv);
        Ahi[r * 136 + lane + 96] = __float2half_rn(v3 * inv);
    }
    __syncthreads();   // E dead; A ready

    // ---------------- Phase 2: out = gamma * (A @ V) + x ----------------
    auto loadV = [&](int s, int ci) {
        const uint32_t stg = sb + s * VST_B;
        const int c0 = ci * 32;
#pragma unroll
        for (int t = 0; t < 2; t++) {
            const int idx = tid + t * 256;
            const int row = idx >> 2, seg = idx & 3;
            const uint32_t doff = (uint32_t)(row * 80 + seg * 16);
            cp16(stg + doff, v16 + (size_t)row * Cn + c0 + seg * 8);
        }
        asm volatile("cp.async.commit_group;" ::: "memory");
    };

    loadV(0, 0);
    loadV(1, 1);

    // persistent A fragments: warp owns 16 h-rows
    const int h0 = wid * 16;
    uint32_t Ah[8][4];
    {
        const uint32_t abase = sb + A_OFF +
            (uint32_t)(((h0 + (lane & 15)) * 136 + (lane >> 4) * 8) * 2);
#pragma unroll
        for (int ks = 0; ks < 8; ks++)
            ldsm_x4(Ah[ks], abase + ks * 32);
    }

    const float gam = gamma_p[0];
    const uint32_t v_lane = (uint32_t)(((lane & 7) + ((lane >> 3) & 1) * 8) * 80 +
                                       (lane >> 4) * 16);

    for (int ci = 0; ci < 16; ci++) {
        const int s = ci & 1;
        if (ci < 14) asm volatile("cp.async.wait_group 1;" ::: "memory");
        else         asm volatile("cp.async.wait_group 0;" ::: "memory");
        __syncthreads();

        const uint32_t vs = sb + s * VST_B;

        float acc2[4][4];
#pragma unroll
        for (int j = 0; j < 4; j++)
#pragma unroll
            for (int q = 0; q < 4; q++) acc2[j][q] = 0.f;

#pragma unroll
        for (int ks = 0; ks < 8; ks++) {
            const uint32_t vrow = vs + (uint32_t)(ks * 16 * 80) + v_lane;
            uint32_t bh0[4], bh1[4];
            ldsm_x4_t(bh0, vrow);
            ldsm_x4_t(bh1, vrow + 32);
            mma_f16(acc2[0], Ah[ks], bh0);
            mma_f16(acc2[1], Ah[ks], bh0 + 2);
            mma_f16(acc2[2], Ah[ks], bh1);
            mma_f16(acc2[3], Ah[ks], bh1 + 2);
        }
        __syncthreads();
        if (ci + 2 < 16) loadV(s, ci + 2);

        const int hr = h0 + (lane >> 2);
#pragma unroll
        for (int j = 0; j < 4; j++) {
            const int c = ci * 32 + j * 8 + (lane & 3) * 2;
            const size_t o0 = ((size_t)(b * Hn + hr)     * Wn + w) * Cn + c;
            const size_t o1 = ((size_t)(b * Hn + hr + 8) * Wn + w) * Cn + c;
            float2 x0 = *(const float2*)(x + o0);
            float2 x1 = *(const float2*)(x + o1);
            float2 r0, r1;
            r0.x = fmaf(gam, acc2[j][0], x0.x);
            r0.y = fmaf(gam, acc2[j][1], x0.y);
            r1.x = fmaf(gam, acc2[j][2], x1.x);
            r1.y = fmaf(gam, acc2[j][3], x1.y);
            *(float2*)(out + o0) = r0;
            *(float2*)(out + o1) = r1;
        }
    }
}

// ---------------------------------------------------------------------------
extern "C" void kernel_launch(void* const* d_in, const int* in_sizes, int n_in,
                              void* d_out, int out_size)
{
    const float* x  = (const float*)d_in[0];
    const float* Wq = (const float*)d_in[1];
    const float* Wk = (const float*)d_in[2];
    const float* Wv = (const float*)d_in[3];
    const float* gm = (const float*)d_in[4];
    float* out = (float*)d_out;

    split_x<<<(size_t)MTOT * Cn / 4 / 256, 256>>>((const float4*)x);
    split_w<<<(size_t)1536 * Cn / 4 / 256, 256>>>(Wq, Wk, Wv);

    cudaFuncSetAttribute(qk_mma, cudaFuncAttributeMaxDynamicSharedMemorySize, 2 * STG_B);
    dim3 grid_qk(8, MTOT / 128);
    qk_mma<<<grid_qk, 256, 2 * STG_B>>>();

    cudaFuncSetAttribute(v_mma, cudaFuncAttributeMaxDynamicSharedMemorySize, 2 * VSTG_B);
    dim3 grid_v(4, MTOT / 128);
    v_mma<<<grid_v, 256, 2 * VSTG_B>>>();

    cudaFuncSetAttribute(cc_attn, cudaFuncAttributeMaxDynamicSharedMemorySize, CC_SMEM);
    cc_attn<<<NCOL, 256, CC_SMEM>>>(x, gm, out);
}

// round 7
// speedup vs baseline: 4.0402x; 1.4372x over previous
#include <cuda_runtime.h>
#include <cuda_bf16.h>
#include <cuda_fp16.h>
#include <cstdint>

#define Bn 8
#define Hn 128
#define Wn 128
#define Cn 512
#define NCOL (Bn*Wn)          /* 1024 (b,w) columns */
#define MTOT (Bn*Hn*Wn)       /* 131072 rows */

// x transposed to [B,W,H,C], fp16 hi/lo (exact split of fp32 x)
__device__ __half g_xth[(size_t)NCOL * Hn * Cn];
__device__ __half g_xtl[(size_t)NCOL * Hn * Cn];
// Wv fp16
__device__ __half g_wv16[(size_t)512 * Cn];
// M^T = (Wq^T Wk)^T stored [j][c], fp16 hi/lo
__device__ __half g_mhi[(size_t)512 * 512];
__device__ __half g_mlo[(size_t)512 * 512];
// s = x@M ("q" equivalent) fp16 hi/lo, v fp16; [B,W,H,C]
__device__ __half g_qh[(size_t)NCOL * Hn * Cn];
__device__ __half g_ql[(size_t)NCOL * Hn * Cn];
__device__ __half g_v16[(size_t)NCOL * Hn * Cn];

__device__ __forceinline__ uint32_t smem_u32(const void* p) {
    uint32_t a;
    asm("{ .reg .u64 t; cvta.to.shared.u64 t, %1; cvt.u32.u64 %0, t; }" : "=r"(a) : "l"(p));
    return a;
}
__device__ __forceinline__ void ldsm_x4(uint32_t* r, uint32_t addr) {
    asm volatile("ldmatrix.sync.aligned.m8n8.x4.shared.b16 {%0,%1,%2,%3}, [%4];"
                 : "=r"(r[0]), "=r"(r[1]), "=r"(r[2]), "=r"(r[3]) : "r"(addr));
}
__device__ __forceinline__ void ldsm_x2(uint32_t* r, uint32_t addr) {
    asm volatile("ldmatrix.sync.aligned.m8n8.x2.shared.b16 {%0,%1}, [%2];"
                 : "=r"(r[0]), "=r"(r[1]) : "r"(addr));
}
__device__ __forceinline__ void ldsm_x4_t(uint32_t* r, uint32_t addr) {
    asm volatile("ldmatrix.sync.aligned.m8n8.x4.trans.shared.b16 {%0,%1,%2,%3}, [%4];"
                 : "=r"(r[0]), "=r"(r[1]), "=r"(r[2]), "=r"(r[3]) : "r"(addr));
}
__device__ __forceinline__ void mma_f16(float* c, const uint32_t* a, const uint32_t* b) {
    asm volatile("mma.sync.aligned.m16n8k16.row.col.f32.f16.f16.f32 "
                 "{%0,%1,%2,%3}, {%4,%5,%6,%7}, {%8,%9}, {%0,%1,%2,%3};"
                 : "+f"(c[0]), "+f"(c[1]), "+f"(c[2]), "+f"(c[3])
                 : "r"(a[0]), "r"(a[1]), "r"(a[2]), "r"(a[3]), "r"(b[0]), "r"(b[1]));
}
__device__ __forceinline__ void cp16(uint32_t dst, const void* src) {
    asm volatile("cp.async.cg.shared.global [%0], [%1], 16;"
                 :: "r"(dst), "l"(__cvta_generic_to_global(src)) : "memory");
}
__device__ __forceinline__ uint32_t pack2h(float a, float b) {
    __half2 h = __floats2half2_rn(a, b);
    return *(uint32_t*)&h;
}

// ---------------------------------------------------------------------------
// split_xt: x [B,H,W,C] fp32 -> xth/xtl fp16 hi/lo in [B,W,H,C].
// One block per input row (b,h,w); 128 threads x float4.
// ---------------------------------------------------------------------------
__global__ __launch_bounds__(128)
void split_xt(const float* __restrict__ x)
{
    const int m = blockIdx.x;              // (b*128+h)*128+w
    const int b = m >> 14, h = (m >> 7) & 127, w = m & 127;
    const size_t orow = ((size_t)(b * Wn + w) * Hn + h) * Cn;
    const int c = threadIdx.x * 4;
    float4 v = *(const float4*)(x + (size_t)m * Cn + c);
    float h0 = __half2float(__float2half_rn(v.x));
    float h1 = __half2float(__float2half_rn(v.y));
    float h2 = __half2float(__float2half_rn(v.z));
    float h3 = __half2float(__float2half_rn(v.w));
    uint2 uh, ul;
    uh.x = pack2h(v.x, v.y);          uh.y = pack2h(v.z, v.w);
    ul.x = pack2h(v.x - h0, v.y - h1); ul.y = pack2h(v.z - h2, v.w - h3);
    *(uint2*)(g_xth + orow + c) = uh;
    *(uint2*)(g_xtl + orow + c) = ul;
}

__global__ __launch_bounds__(256)
void split_wv(const float4* __restrict__ Wv)
{
    size_t i = (size_t)blockIdx.x * 256 + threadIdx.x;   // over 512*512/4
    float4 v = Wv[i];
    uint2 uf;
    uf.x = pack2h(v.x, v.y);  uf.y = pack2h(v.z, v.w);
    ((uint2*)g_wv16)[i] = uf;
}

// ---------------------------------------------------------------------------
// wm_mma: M = Wq^T @ Wk (fp32 FFMA), output transposed Mt[j][c] as fp16 hi/lo.
// 64x64 tiles, grid (8,8), 256 threads, 4x4 per thread.
// ---------------------------------------------------------------------------
__global__ __launch_bounds__(256)
void wm_mma(const float* __restrict__ Wq, const float* __restrict__ Wk)
{
    __shared__ float As[16 * 68];   // [r][c-tile]
    __shared__ float Bs[16 * 68];   // [r][j-tile]
    const int tid = threadIdx.x;
    const int m0 = blockIdx.y * 64;      // c index (col of Wq)
    const int n0 = blockIdx.x * 64;      // j index (col of Wk)
    const int tm = (tid >> 4) * 4;
    const int tn = (tid & 15) * 4;
    const int lrow = tid >> 4;           // 0..15
    const int lcol = (tid & 15) * 4;

    float acc[4][4];
#pragma unroll
    for (int i = 0; i < 4; i++)
#pragma unroll
        for (int j = 0; j < 4; j++) acc[i][j] = 0.f;

    for (int r0 = 0; r0 < 512; r0 += 16) {
        *(float4*)&As[lrow * 68 + lcol] = *(const float4*)(Wq + (size_t)(r0 + lrow) * Cn + m0 + lcol);
        *(float4*)&Bs[lrow * 68 + lcol] = *(const float4*)(Wk + (size_t)(r0 + lrow) * Cn + n0 + lcol);
        __syncthreads();
#pragma unroll
        for (int kk = 0; kk < 16; kk++) {
            float4 a4 = *(const float4*)&As[kk * 68 + tm];
            float4 b4 = *(const float4*)&Bs[kk * 68 + tn];
            float a[4] = {a4.x, a4.y, a4.z, a4.w};
            float b[4] = {b4.x, b4.y, b4.z, b4.w};
#pragma unroll
            for (int i = 0; i < 4; i++)
#pragma unroll
                for (int j = 0; j < 4; j++)
                    acc[i][j] = fmaf(a[i], b[j], acc[i][j]);
        }
        __syncthreads();
    }

    // write Mt[j][c] fp16 hi/lo
#pragma unroll
    for (int j = 0; j < 4; j++) {
        const size_t base = (size_t)(n0 + tn + j) * 512 + m0 + tm;
        float e0 = acc[0][j], e1 = acc[1][j], e2 = acc[2][j], e3 = acc[3][j];
        float h0 = __half2float(__float2half_rn(e0));
        float h1 = __half2float(__float2half_rn(e1));
        float h2 = __half2float(__float2half_rn(e2));
        float h3 = __half2float(__float2half_rn(e3));
        *(uint32_t*)(g_mhi + base)     = pack2h(e0, e1);
        *(uint32_t*)(g_mhi + base + 2) = pack2h(e2, e3);
        *(uint32_t*)(g_mlo + base)     = pack2h(e0 - h0, e1 - h1);
        *(uint32_t*)(g_mlo + base + 2) = pack2h(e2 - h2, e3 - h3);
    }
}

// ---------------------------------------------------------------------------
// xm_mma: s = x @ M, 3-term fp16 split (A = xth/xtl, B = Mt hi/lo).
// CTA 128x128, 2-stage, 2 CTAs/SM. Output s fp16 hi/lo, rows = [B,W,H] linear.
// ---------------------------------------------------------------------------
#define KCH 32
#define NCHUNK (Cn / KCH)         /* 16 */
#define TILE_B 10240              /* 128 rows x 80B */
#define STG_B  (4 * TILE_B)

__global__ __launch_bounds__(256, 2)
void xm_mma()
{
    extern __shared__ char sm[];
    const uint32_t sb = smem_u32(sm);
    const int tid  = threadIdx.x;
    const int wid  = tid >> 5, lane = tid & 31;
    const int m0   = blockIdx.y * 128;      // row block in [B,W,H] linear
    const int n0g  = blockIdx.x * 128;      // 0..511

    const int warp_m = (wid >> 2) * 64;
    const int warp_n = (wid & 3) * 32;

    const __half* xa_hi = g_xth + (size_t)m0 * Cn;
    const __half* xa_lo = g_xtl + (size_t)m0 * Cn;
    const __half* wb_hi = g_mhi + (size_t)n0g * Cn;
    const __half* wb_lo = g_mlo + (size_t)n0g * Cn;

    auto load_chunk = [&](int s, int k0) {
        const uint32_t stg = sb + s * STG_B;
#pragma unroll
        for (int t = 0; t < 2; t++) {
            const int idx = tid + t * 256;
            const int row = idx >> 2, seg = idx & 3;
            const uint32_t doff = (uint32_t)(row * 80 + seg * 16);
            const size_t goff = (size_t)row * Cn + k0 + seg * 8;
            cp16(stg + doff,              xa_hi + goff);
            cp16(stg + 2*TILE_B + doff,   wb_hi + goff);
            cp16(stg + TILE_B + doff,     xa_lo + goff);
            cp16(stg + 3*TILE_B + doff,   wb_lo + goff);
        }
        asm volatile("cp.async.commit_group;" ::: "memory");
    };

    float acc[4][4][4];
#pragma unroll
    for (int i = 0; i < 4; i++)
#pragma unroll
        for (int j = 0; j < 4; j++)
#pragma unroll
            for (int q = 0; q < 4; q++) acc[i][j][q] = 0.f;

    const uint32_t a_lane = (uint32_t)((lane & 15) * 80 + (lane >> 4) * 16);
    const uint32_t b_lane = (uint32_t)((lane & 7) * 80 + ((lane >> 3) & 1) * 16);

    load_chunk(0, 0);
    load_chunk(1, KCH);

    for (int k = 0; k < NCHUNK; k++) {
        const int s = k & 1;
        const uint32_t stg = sb + s * STG_B;

        if (k < NCHUNK - 2) asm volatile("cp.async.wait_group 1;" ::: "memory");
        else                asm volatile("cp.async.wait_group 0;" ::: "memory");
        __syncthreads();

        const uint32_t a_hi_base = stg            + warp_m * 80 + a_lane;
        const uint32_t a_lo_base = stg + TILE_B   + warp_m * 80 + a_lane;
        const uint32_t b_hi_base = stg + 2*TILE_B + warp_n * 80 + b_lane;
        const uint32_t b_lo_base = stg + 3*TILE_B + warp_n * 80 + b_lane;

#pragma unroll
        for (int ks = 0; ks < 2; ks++) {
            uint32_t ah[4][4], bh[4][2];
#pragma unroll
            for (int mf = 0; mf < 4; mf++)
                ldsm_x4(ah[mf], a_hi_base + mf * (16 * 80) + ks * 32);
#pragma unroll
            for (int nf = 0; nf < 4; nf++)
                ldsm_x2(bh[nf], b_hi_base + nf * (8 * 80) + ks * 32);
#pragma unroll
            for (int mf = 0; mf < 4; mf++)
#pragma unroll
                for (int nf = 0; nf < 4; nf++)
                    mma_f16(acc[mf][nf], ah[mf], bh[nf]);

            uint32_t bl[4][2];
#pragma unroll
            for (int nf = 0; nf < 4; nf++)
                ldsm_x2(bl[nf], b_lo_base + nf * (8 * 80) + ks * 32);
#pragma unroll
            for (int mf = 0; mf < 4; mf++)
#pragma unroll
                for (int nf = 0; nf < 4; nf++)
                    mma_f16(acc[mf][nf], ah[mf], bl[nf]);

            uint32_t al[4][4];
#pragma unroll
            for (int mf = 0; mf < 4; mf++)
                ldsm_x4(al[mf], a_lo_base + mf * (16 * 80) + ks * 32);
#pragma unroll
            for (int mf = 0; mf < 4; mf++)
#pragma unroll
                for (int nf = 0; nf < 4; nf++)
                    mma_f16(acc[mf][nf], al[mf], bh[nf]);
        }
        __syncthreads();

        if (k + 2 < NCHUNK) load_chunk(s, (k + 2) * KCH);
    }

    // epilogue: rows are already [B,W,H]-linear — contiguous store
    const int col0 = n0g + warp_n;
    const int g   = lane >> 2;
    const int c2i = (lane & 3) * 2;
#pragma unroll
    for (int mf = 0; mf < 4; mf++) {
        const int r = m0 + warp_m + mf * 16 + g;
        const size_t r0 = (size_t)r * Cn + col0 + c2i;
        const size_t r1 = (size_t)(r + 8) * Cn + col0 + c2i;
#pragma unroll
        for (int nf = 0; nf < 4; nf++) {
            float e0 = acc[mf][nf][0], e1 = acc[mf][nf][1];
            float e2 = acc[mf][nf][2], e3 = acc[mf][nf][3];
            float h0 = __half2float(__float2half_rn(e0));
            float h1 = __half2float(__float2half_rn(e1));
            float h2 = __half2float(__float2half_rn(e2));
            float h3 = __half2float(__float2half_rn(e3));
            *(uint32_t*)(g_qh + r0 + nf * 8) = pack2h(e0, e1);
            *(uint32_t*)(g_ql + r0 + nf * 8) = pack2h(e0 - h0, e1 - h1);
            *(uint32_t*)(g_qh + r1 + nf * 8) = pack2h(e2, e3);
            *(uint32_t*)(g_ql + r1 + nf * 8) = pack2h(e2 - h2, e3 - h3);
        }
    }
}

// ---------------------------------------------------------------------------
// v_mma: v = x @ Wv^T, single fp16. A = xth ([B,W,H] rows), out v16 same rows.
// ---------------------------------------------------------------------------
#define VSTG_B (2 * TILE_B)

__global__ __launch_bounds__(256, 2)
void v_mma()
{
    extern __shared__ char sm[];
    const uint32_t sb = smem_u32(sm);
    const int tid  = threadIdx.x;
    const int wid  = tid >> 5, lane = tid & 31;
    const int m0   = blockIdx.y * 128;
    const int n0v  = blockIdx.x * 128;

    const int warp_m = (wid >> 2) * 64;
    const int warp_n = (wid & 3) * 32;

    const __half* xa = g_xth  + (size_t)m0 * Cn;
    const __half* wb = g_wv16 + (size_t)n0v * Cn;

    auto load_chunk = [&](int s, int k0) {
        const uint32_t stg = sb + s * VSTG_B;
#pragma unroll
        for (int t = 0; t < 2; t++) {
            const int idx = tid + t * 256;
            const int row = idx >> 2, seg = idx & 3;
            const uint32_t doff = (uint32_t)(row * 80 + seg * 16);
            const size_t goff = (size_t)row * Cn + k0 + seg * 8;
            cp16(stg + doff,          xa + goff);
            cp16(stg + TILE_B + doff, wb + goff);
        }
        asm volatile("cp.async.commit_group;" ::: "memory");
    };

    float acc[4][4][4];
#pragma unroll
    for (int i = 0; i < 4; i++)
#pragma unroll
        for (int j = 0; j < 4; j++)
#pragma unroll
            for (int q = 0; q < 4; q++) acc[i][j][q] = 0.f;

    const uint32_t a_lane = (uint32_t)((lane & 15) * 80 + (lane >> 4) * 16);
    const uint32_t b_lane = (uint32_t)((lane & 7) * 80 + ((lane >> 3) & 1) * 16);

    load_chunk(0, 0);
    load_chunk(1, KCH);

    for (int k = 0; k < NCHUNK; k++) {
        const int s = k & 1;
        const uint32_t stg = sb + s * VSTG_B;

        if (k < NCHUNK - 2) asm volatile("cp.async.wait_group 1;" ::: "memory");
        else                asm volatile("cp.async.wait_group 0;" ::: "memory");
        __syncthreads();

        const uint32_t a_base = stg          + warp_m * 80 + a_lane;
        const uint32_t b_base = stg + TILE_B + warp_n * 80 + b_lane;

#pragma unroll
        for (int ks = 0; ks < 2; ks++) {
            uint32_t ah[4][4], bh[4][2];
#pragma unroll
            for (int mf = 0; mf < 4; mf++)
                ldsm_x4(ah[mf], a_base + mf * (16 * 80) + ks * 32);
#pragma unroll
            for (int nf = 0; nf < 4; nf++)
                ldsm_x2(bh[nf], b_base + nf * (8 * 80) + ks * 32);
#pragma unroll
            for (int mf = 0; mf < 4; mf++)
#pragma unroll
                for (int nf = 0; nf < 4; nf++)
                    mma_f16(acc[mf][nf], ah[mf], bh[nf]);
        }
        __syncthreads();

        if (k + 2 < NCHUNK) load_chunk(s, (k + 2) * KCH);
    }

    const int col0 = n0v + warp_n;
    const int g   = lane >> 2;
    const int c2i = (lane & 3) * 2;
#pragma unroll
    for (int mf = 0; mf < 4; mf++) {
        const int r = m0 + warp_m + mf * 16 + g;
        const size_t r0 = (size_t)r * Cn + col0 + c2i;
        const size_t r1 = (size_t)(r + 8) * Cn + col0 + c2i;
#pragma unroll
        for (int nf = 0; nf < 4; nf++) {
            *(uint32_t*)(g_v16 + r0 + nf * 8) = pack2h(acc[mf][nf][0], acc[mf][nf][1]);
            *(uint32_t*)(g_v16 + r1 + nf * 8) = pack2h(acc[mf][nf][2], acc[mf][nf][3]);
        }
    }
}

// ---------------------------------------------------------------------------
// cc_attn: E = s x^T (3-term fp16; s = xM as Q, x as K), softmax, AV fp16.
// ---------------------------------------------------------------------------
#define A_OFF   65536
#define VST_B   10240
#define CC_SMEM 100352

__global__ __launch_bounds__(256, 2)
void cc_attn(const float* __restrict__ x, const float* __restrict__ gamma_p,
             float* __restrict__ out)
{
    extern __shared__ char sm[];
    const uint32_t sb = smem_u32(sm);
    float* E = (float*)sm;
    __half* Ahi = (__half*)(sm + A_OFF);

    const int bw  = blockIdx.x;
    const int b   = bw >> 7;
    const int w   = bw & 127;
    const int tid = threadIdx.x;
    const int wid = tid >> 5, lane = tid & 31;

    const size_t colbase = (size_t)bw * (Hn * Cn);
    const __half* qh = g_qh + colbase;
    const __half* ql = g_ql + colbase;
    const __half* kh = g_xth + colbase;
    const __half* kl = g_xtl + colbase;
    const __half* v16 = g_v16 + colbase;

    const int warp_m = (wid >> 2) * 64;
    const int warp_n = (wid & 3) * 32;

    auto load_chunk = [&](int s, int k0) {
        const uint32_t stg = sb + s * STG_B;
#pragma unroll
        for (int t = 0; t < 2; t++) {
            const int idx = tid + t * 256;
            const int row = idx >> 2, seg = idx & 3;
            const uint32_t doff = (uint32_t)(row * 80 + seg * 16);
            const size_t goff = (size_t)row * Cn + k0 + seg * 8;
            cp16(stg + doff,              qh + goff);
            cp16(stg + 2*TILE_B + doff,   kh + goff);
            cp16(stg + TILE_B + doff,     ql + goff);
            cp16(stg + 3*TILE_B + doff,   kl + goff);
        }
        asm volatile("cp.async.commit_group;" ::: "memory");
    };

    float acc[4][4][4];
#pragma unroll
    for (int i = 0; i < 4; i++)
#pragma unroll
        for (int j = 0; j < 4; j++)
#pragma unroll
            for (int q = 0; q < 4; q++) acc[i][j][q] = 0.f;

    const uint32_t a_lane = (uint32_t)((lane & 15) * 80 + (lane >> 4) * 16);
    const uint32_t b_lane = (uint32_t)((lane & 7) * 80 + ((lane >> 3) & 1) * 16);

    load_chunk(0, 0);
    load_chunk(1, KCH);

    for (int k = 0; k < NCHUNK; k++) {
        const int s = k & 1;
        const uint32_t stg = sb + s * STG_B;

        if (k < NCHUNK - 2) asm volatile("cp.async.wait_group 1;" ::: "memory");
        else                asm volatile("cp.async.wait_group 0;" ::: "memory");
        __syncthreads();

        const uint32_t a_hi_base = stg            + warp_m * 80 + a_lane;
        const uint32_t a_lo_base = stg + TILE_B   + warp_m * 80 + a_lane;
        const uint32_t b_hi_base = stg + 2*TILE_B + warp_n * 80 + b_lane;
        const uint32_t b_lo_base = stg + 3*TILE_B + warp_n * 80 + b_lane;

#pragma unroll
        for (int ks = 0; ks < 2; ks++) {
            uint32_t ah[4][4], bh[4][2];
#pragma unroll
            for (int mf = 0; mf < 4; mf++)
                ldsm_x4(ah[mf], a_hi_base + mf * (16 * 80) + ks * 32);
#pragma unroll
            for (int nf = 0; nf < 4; nf++)
                ldsm_x2(bh[nf], b_hi_base + nf * (8 * 80) + ks * 32);
#pragma unroll
            for (int mf = 0; mf < 4; mf++)
#pragma unroll
                for (int nf = 0; nf < 4; nf++)
                    mma_f16(acc[mf][nf], ah[mf], bh[nf]);

            uint32_t bl[4][2];
#pragma unroll
            for (int nf = 0; nf < 4; nf++)
                ldsm_x2(bl[nf], b_lo_base + nf * (8 * 80) + ks * 32);
#pragma unroll
            for (int mf = 0; mf < 4; mf++)
#pragma unroll
                for (int nf = 0; nf < 4; nf++)
                    mma_f16(acc[mf][nf], ah[mf], bl[nf]);

            uint32_t al[4][4];
#pragma unroll
            for (int mf = 0; mf < 4; mf++)
                ldsm_x4(al[mf], a_lo_base + mf * (16 * 80) + ks * 32);
#pragma unroll
            for (int mf = 0; mf < 4; mf++)
#pragma unroll
                for (int nf = 0; nf < 4; nf++)
                    mma_f16(acc[mf][nf], al[mf], bh[nf]);
        }
        __syncthreads();

        if (k + 2 < NCHUNK) load_chunk(s, (k + 2) * KCH);
    }

    const float NEG_INF = __int_as_float(0xff800000);
    {
        const int gr  = lane >> 2;
        const int c2i = (lane & 3) * 2;
#pragma unroll
        for (int mf = 0; mf < 4; mf++) {
            const int h0r = warp_m + mf * 16 + gr;
            const int h1r = h0r + 8;
#pragma unroll
            for (int nf = 0; nf < 4; nf++) {
                const int gg = warp_n + nf * 8 + c2i;
                E[h0r * 128 + gg    ] = (h0r == gg    ) ? NEG_INF : acc[mf][nf][0];
                E[h0r * 128 + gg + 1] = (h0r == gg + 1) ? NEG_INF : acc[mf][nf][1];
                E[h1r * 128 + gg    ] = (h1r == gg    ) ? NEG_INF : acc[mf][nf][2];
                E[h1r * 128 + gg + 1] = (h1r == gg + 1) ? NEG_INF : acc[mf][nf][3];
            }
        }
    }
    __syncthreads();

    for (int r = wid; r < 128; r += 8) {
        float* row = E + r * 128;
        float v0 = row[lane], v1 = row[lane + 32], v2 = row[lane + 64], v3 = row[lane + 96];
        float mx = fmaxf(fmaxf(v0, v1), fmaxf(v2, v3));
#pragma unroll
        for (int o = 16; o > 0; o >>= 1) mx = fmaxf(mx, __shfl_xor_sync(0xffffffffu, mx, o));
        v0 = __expf(v0 - mx); v1 = __expf(v1 - mx);
        v2 = __expf(v2 - mx); v3 = __expf(v3 - mx);
        float s = v0 + v1 + v2 + v3;
#pragma unroll
        for (int o = 16; o > 0; o >>= 1) s += __shfl_xor_sync(0xffffffffu, s, o);
        const float inv = 1.f / s;
        Ahi[r * 136 + lane     ] = __float2half_rn(v0 * inv);
        Ahi[r * 136 + lane + 32] = __float2half_rn(v1 * inv);
        Ahi[r * 136 + lane + 64] = __float2half_rn(v2 * inv);
        Ahi[r * 136 + lane + 96] = __float2half_rn(v3 * inv);
    }
    __syncthreads();

    auto loadV = [&](int s, int ci) {
        const uint32_t stg = sb + s * VST_B;
        const int c0 = ci * 32;
#pragma unroll
        for (int t = 0; t < 2; t++) {
            const int idx = tid + t * 256;
            const int row = idx >> 2, seg = idx & 3;
            const uint32_t doff = (uint32_t)(row * 80 + seg * 16);
            cp16(stg + doff, v16 + (size_t)row * Cn + c0 + seg * 8);
        }
        asm volatile("cp.async.commit_group;" ::: "memory");
    };

    loadV(0, 0);
    loadV(1, 1);

    const int h0 = wid * 16;
    uint32_t Ah[8][4];
    {
        const uint32_t abase = sb + A_OFF +
            (uint32_t)(((h0 + (lane & 15)) * 136 + (lane >> 4) * 8) * 2);
#pragma unroll
        for (int ks = 0; ks < 8; ks++)
            ldsm_x4(Ah[ks], abase + ks * 32);
    }

    const float gam = gamma_p[0];
    const uint32_t v_lane = (uint32_t)(((lane & 7) + ((lane >> 3) & 1) * 8) * 80 +
                                       (lane >> 4) * 16);

    for (int ci = 0; ci < 16; ci++) {
        const int s = ci & 1;
        if (ci < 14) asm volatile("cp.async.wait_group 1;" ::: "memory");
        else         asm volatile("cp.async.wait_group 0;" ::: "memory");
        __syncthreads();

        const uint32_t vs = sb + s * VST_B;

        float acc2[4][4];
#pragma unroll
        for (int j = 0; j < 4; j++)
#pragma unroll
            for (int q = 0; q < 4; q++) acc2[j][q] = 0.f;

#pragma unroll
        for (int ks = 0; ks < 8; ks++) {
            const uint32_t vrow = vs + (uint32_t)(ks * 16 * 80) + v_lane;
            uint32_t bh0[4], bh1[4];
            ldsm_x4_t(bh0, vrow);
            ldsm_x4_t(bh1, vrow + 32);
            mma_f16(acc2[0], Ah[ks], bh0);
            mma_f16(acc2[1], Ah[ks], bh0 + 2);
            mma_f16(acc2[2], Ah[ks], bh1);
            mma_f16(acc2[3], Ah[ks], bh1 + 2);
        }
        __syncthreads();
        if (ci + 2 < 16) loadV(s, ci + 2);

        const int hr = h0 + (lane >> 2);
#pragma unroll
        for (int j = 0; j < 4; j++) {
            const int c = ci * 32 + j * 8 + (lane & 3) * 2;
            const size_t o0 = ((size_t)(b * Hn + hr)     * Wn + w) * Cn + c;
            const size_t o1 = ((size_t)(b * Hn + hr + 8) * Wn + w) * Cn + c;
            float2 x0 = *(const float2*)(x + o0);
            float2 x1 = *(const float2*)(x + o1);
            float2 r0, r1;
            r0.x = fmaf(gam, acc2[j][0], x0.x);
            r0.y = fmaf(gam, acc2[j][1], x0.y);
            r1.x = fmaf(gam, acc2[j][2], x1.x);
            r1.y = fmaf(gam, acc2[j][3], x1.y);
            *(float2*)(out + o0) = r0;
            *(float2*)(out + o1) = r1;
        }
    }
}

// ---------------------------------------------------------------------------
extern "C" void kernel_launch(void* const* d_in, const int* in_sizes, int n_in,
                              void* d_out, int out_size)
{
    const float* x  = (const float*)d_in[0];
    const float* Wq = (const float*)d_in[1];
    const float* Wk = (const float*)d_in[2];
    const float* Wv = (const float*)d_in[3];
    const float* gm = (const float*)d_in[4];
    float* out = (float*)d_out;

    split_xt<<<MTOT, 128>>>(x);
    split_wv<<<512 * 512 / 4 / 256, 256>>>((const float4*)Wv);
    wm_mma<<<dim3(8, 8), 256>>>(Wq, Wk);

    cudaFuncSetAttribute(xm_mma, cudaFuncAttributeMaxDynamicSharedMemorySize, 2 * STG_B);
    xm_mma<<<dim3(4, NCOL * Hn / 128), 256, 2 * STG_B>>>();

    cudaFuncSetAttribute(v_mma, cudaFuncAttributeMaxDynamicSharedMemorySize, 2 * VSTG_B);
    v_mma<<<dim3(4, NCOL * Hn / 128), 256, 2 * VSTG_B>>>();

    cudaFuncSetAttribute(cc_attn, cudaFuncAttributeMaxDynamicSharedMemorySize, CC_SMEM);
    cc_attn<<<NCOL, 256, CC_SMEM>>>(x, gm, out);
}